// round 13
// baseline (speedup 1.0000x reference)
#include <cuda_runtime.h>
#include <cuda_fp16.h>
#include <cstdint>

// ---------------------------------------------------------------------------
// UnpoolWithSkip — fp16 m16n8k16 GEMMs reading fp32 A DIRECTLY (conversion
// fused into the consumer: LDS.64 fp32 pairs -> __floats2half2). B is fp16
// (tiny transposed weights). Eliminates both f2h kernels (+603 MB round-trip).
// 128x128 tile, 256 thr, warp 32x64, 2-stage cp.async, fp32 C scratch,
// fused BN stats, fp32 fuse. GEMM2 (skip) first so g_h stays L2-warm.
// ---------------------------------------------------------------------------

#define EPS 1e-5f

static constexpr int N_IN  = 65536;
static constexpr int N_OUT = 262144;
static constexpr int C     = 256;

__device__ float  g_h[(size_t)N_IN  * C];
__device__ float  g_s[(size_t)N_OUT * C];
__device__ __half g_wt_proj[(size_t)C * 512];
__device__ __half g_wt_skip[(size_t)C * 256];
__device__ float g_sum_p[C], g_ssq_p[C];
__device__ float g_sum_s[C], g_ssq_s[C];
__device__ float g_a_p[C], g_b_p[C];
__device__ float g_a_s[C], g_b_s[C];

// ---------------------------------------------------------------------------
__device__ __forceinline__ void mma_f16(float* c, const uint32_t* a, const uint32_t* b) {
    asm volatile(
        "mma.sync.aligned.m16n8k16.row.col.f32.f16.f16.f32 "
        "{%0,%1,%2,%3}, {%4,%5,%6,%7}, {%8,%9}, {%0,%1,%2,%3};"
        : "+f"(c[0]), "+f"(c[1]), "+f"(c[2]), "+f"(c[3])
        : "r"(a[0]), "r"(a[1]), "r"(a[2]), "r"(a[3]), "r"(b[0]), "r"(b[1]));
}
__device__ __forceinline__ void ldsm_x4(uint32_t& d0, uint32_t& d1,
                                        uint32_t& d2, uint32_t& d3, uint32_t addr) {
    asm volatile("ldmatrix.sync.aligned.m8n8.x4.shared.b16 {%0,%1,%2,%3}, [%4];"
                 : "=r"(d0), "=r"(d1), "=r"(d2), "=r"(d3) : "r"(addr));
}
__device__ __forceinline__ uint32_t smem_u32(const void* p) {
    uint32_t a;
    asm("{ .reg .u64 t; cvta.to.shared.u64 t, %1; cvt.u32.u64 %0, t; }"
        : "=r"(a) : "l"(p));
    return a;
}
__device__ __forceinline__ uint32_t pack_h2(float2 v) {
    __half2 h = __floats2half2_rn(v.x, v.y);
    return *(uint32_t*)&h;
}

// ---------------------------------------------------------------------------
__global__ void zero_stats_kernel() {
    int c = threadIdx.x;
    g_sum_p[c] = 0.f; g_ssq_p[c] = 0.f;
    g_sum_s[c] = 0.f; g_ssq_s[c] = 0.f;
}

__global__ void transpose_w_kernel(const float* __restrict__ W,
                                   __half* __restrict__ Wt, int K, int N) {
    __shared__ float t[32][33];
    int n0 = blockIdx.x * 32, k0 = blockIdx.y * 32;
    int tx = threadIdx.x, ty = threadIdx.y;
    #pragma unroll
    for (int i = 0; i < 32; i += 8)
        t[ty + i][tx] = W[(size_t)(k0 + ty + i) * N + n0 + tx];
    __syncthreads();
    #pragma unroll
    for (int i = 0; i < 32; i += 8)
        Wt[(size_t)(n0 + ty + i) * K + k0 + tx] = __float2half_rn(t[tx][ty + i]);
}

__global__ void finalize_kernel(
    const float* __restrict__ gamma_p, const float* __restrict__ beta_p,
    const float* __restrict__ gamma_s, const float* __restrict__ beta_s)
{
    int c = threadIdx.x;
    {
        float m = g_sum_p[c] * (1.f / N_IN);
        float v = g_ssq_p[c] * (1.f / N_IN) - m * m;
        float a = gamma_p[c] * rsqrtf(v + EPS);
        g_a_p[c] = a; g_b_p[c] = beta_p[c] - m * a;
    }
    {
        float m = g_sum_s[c] * (1.f / N_OUT);
        float v = g_ssq_s[c] * (1.f / N_OUT) - m * m;
        float a = gamma_s[c] * rsqrtf(v + EPS);
        g_a_s[c] = a; g_b_s[c] = beta_s[c] - m * a;
    }
}

__global__ __launch_bounds__(256) void fuse_out_kernel(
    const int* __restrict__ cluster, float* __restrict__ out)
{
    int idx = blockIdx.x * 256 + threadIdx.x;
    int n  = idx >> 6;
    int c4 = (idx & 63) << 2;
    int k  = __ldg(&cluster[n]);

    float4 h  = *(const float4*)&g_h[(size_t)k * C + c4];
    float4 sv = *(const float4*)&g_s[(size_t)n * C + c4];
    float4 ap = *(const float4*)&g_a_p[c4];
    float4 bp = *(const float4*)&g_b_p[c4];
    float4 as_ = *(const float4*)&g_a_s[c4];
    float4 bs_ = *(const float4*)&g_b_s[c4];

    float4 o;
    o.x = fmaxf(fmaf(ap.x, h.x, bp.x), 0.f) + fmaxf(fmaf(as_.x, sv.x, bs_.x), 0.f);
    o.y = fmaxf(fmaf(ap.y, h.y, bp.y), 0.f) + fmaxf(fmaf(as_.y, sv.y, bs_.y), 0.f);
    o.z = fmaxf(fmaf(ap.z, h.z, bp.z), 0.f) + fmaxf(fmaf(as_.z, sv.z, bs_.z), 0.f);
    o.w = fmaxf(fmaf(ap.w, h.w, bp.w), 0.f) + fmaxf(fmaf(as_.w, sv.w, bs_.w), 0.f);
    *(float4*)&out[(size_t)n * C + c4] = o;
}

// ---------------------------------------------------------------------------
// fp16-MMA GEMM with fp32 A: C[M,256] = A[M,K] @ Bt[256,K]^T + bias.
// A tile: fp32 in smem (cp.async), converted to fp16 frags in consumer.
// B tile: fp16 in smem (cp.async), ldmatrix frags.
// Tile 128x128, BK=64 elems, 256 threads (warps 4m x 2n -> 32x64),
// 2-stage pipeline. Grid (2, M/128).
// ---------------------------------------------------------------------------
static constexpr int A_PADF   = 68;                        // floats per A row
static constexpr int A_ROWB   = A_PADF * 4;                // 272 B
static constexpr uint32_t A_SB = 128u * A_ROWB;            // 34816 B
static constexpr int B_PADH   = 72;                        // halfs per B row
static constexpr int B_ROWB   = B_PADH * 2;                // 144 B
static constexpr uint32_t B_BYTES = 128u * B_ROWB;         // 18432 B
static constexpr uint32_t STAGE_BYTES = A_SB + B_BYTES;    // 53248 B
static constexpr uint32_t SMEM_BYTES = STAGE_BYTES * 2;    // 106496 B

__device__ __forceinline__ void load_tile_async(
    const float* __restrict__ A, const __half* __restrict__ Bt, int K,
    int m0, int n0, int kt, uint32_t sbase, int tid)
{
    // A fp32: 128 rows x 64 floats = 2048 x 16B chunks -> 8/thread
    #pragma unroll
    for (int p = 0; p < 8; p++) {
        int idx = tid + p * 256;
        int row = idx >> 4, ch = idx & 15;
        const float* ga = A + (size_t)(m0 + row) * K + kt * 64 + ch * 4;
        uint32_t sa = sbase + row * A_ROWB + ch * 16;
        asm volatile("cp.async.cg.shared.global [%0], [%1], 16;"
                     :: "r"(sa), "l"(ga) : "memory");
    }
    // B fp16: 128 rows x 64 halfs = 1024 x 16B chunks -> 4/thread
    #pragma unroll
    for (int p = 0; p < 4; p++) {
        int idx = tid + p * 256;
        int row = idx >> 3, ch = idx & 7;
        const __half* gb = Bt + (size_t)(n0 + row) * K + kt * 64 + ch * 8;
        uint32_t sb = sbase + A_SB + row * B_ROWB + ch * 16;
        asm volatile("cp.async.cg.shared.global [%0], [%1], 16;"
                     :: "r"(sb), "l"(gb) : "memory");
    }
    asm volatile("cp.async.commit_group;" ::: "memory");
}

__global__ __launch_bounds__(256) void mma_gemm_kernel(
    const float* __restrict__ A, const __half* __restrict__ Bt,
    const float* __restrict__ bias, float* __restrict__ Cout,
    int K, float* __restrict__ sum, float* __restrict__ ssq)
{
    extern __shared__ char smem_raw[];
    __shared__ float ssum[128], sssq[128];

    const int tid  = threadIdx.x;
    const int lane = tid & 31;
    const int wid  = tid >> 5;
    const int wm   = wid & 3;
    const int wn   = wid >> 2;
    const int g    = lane >> 2;
    const int t    = lane & 3;

    const int n0 = blockIdx.x * 128;
    const int m0 = blockIdx.y * 128;

    const uint32_t sbase = smem_u32(smem_raw);

    if (tid < 128) { ssum[tid] = 0.f; sssq[tid] = 0.f; }

    float acc[2][8][4];
    #pragma unroll
    for (int i = 0; i < 2; i++)
        #pragma unroll
        for (int j = 0; j < 8; j++)
            #pragma unroll
            for (int q = 0; q < 4; q++) acc[i][j][q] = 0.f;

    const int KT = K >> 6;            // BK = 64 elems
    const int mw = wm * 32;
    const int nw = wn * 64;

    // A fragment source rows (fp32 smem, float2 index): rows mw+i*16+g (+8)
    // B ldmatrix per-lane offsets (fp16 region)
    const int lm = lane >> 3;
    const int lr = lane & 7;
    uint32_t b_off[4];
    #pragma unroll
    for (int p = 0; p < 4; p++)
        b_off[p] = A_SB
                 + (uint32_t)((nw + 16 * p + 8 * (lm >> 1) + lr) * B_ROWB
                              + (lm & 1) * 16);

    load_tile_async(A, Bt, K, m0, n0, 0, sbase, tid);

    int buf = 0;
    for (int kt = 0; kt < KT; kt++) {
        if (kt + 1 < KT) {
            load_tile_async(A, Bt, K, m0, n0, kt + 1,
                            sbase + (uint32_t)(buf ^ 1) * STAGE_BYTES, tid);
            asm volatile("cp.async.wait_group 1;" ::: "memory");
        } else {
            asm volatile("cp.async.wait_group 0;" ::: "memory");
        }
        __syncthreads();

        const uint32_t stg = sbase + (uint32_t)buf * STAGE_BYTES;
        const float2* Af = (const float2*)(smem_raw + (size_t)buf * STAGE_BYTES);
        // float2 row stride = A_PADF/2 = 34

        #pragma unroll
        for (int ks = 0; ks < 4; ks++) {
            const int kf2 = ks * 8 + t;          // float2 index of k pair 2t
            uint32_t af[2][4];
            #pragma unroll
            for (int i = 0; i < 2; i++) {
                const int r0 = (mw + i * 16 + g) * (A_PADF / 2);
                const int r1 = r0 + 8 * (A_PADF / 2);
                af[i][0] = pack_h2(Af[r0 + kf2]);
                af[i][1] = pack_h2(Af[r1 + kf2]);
                af[i][2] = pack_h2(Af[r0 + kf2 + 4]);
                af[i][3] = pack_h2(Af[r1 + kf2 + 4]);
            }
            const uint32_t kb = ks * 32;         // 16 halfs = 32 B in B region
            uint32_t bf[8][2];
            #pragma unroll
            for (int p = 0; p < 4; p++)
                ldsm_x4(bf[2*p][0], bf[2*p][1], bf[2*p+1][0], bf[2*p+1][1],
                        stg + b_off[p] + kb);
            #pragma unroll
            for (int i = 0; i < 2; i++)
                #pragma unroll
                for (int j = 0; j < 8; j++)
                    mma_f16(acc[i][j], af[i], bf[j]);
        }
        __syncthreads();
        buf ^= 1;
    }

    // ---- Epilogue: bias add, float2 stores, fp32 BN stats ----
    #pragma unroll
    for (int j = 0; j < 8; j++) {
        const int cl = nw + j * 8 + 2 * t;
        const int cg = n0 + cl;
        const float b0v = __ldg(&bias[cg]);
        const float b1v = __ldg(&bias[cg + 1]);
        float s0 = 0.f, s1 = 0.f, q0 = 0.f, q1 = 0.f;
        #pragma unroll
        for (int i = 0; i < 2; i++) {
            const int row = m0 + mw + i * 16 + g;
            float v00 = acc[i][j][0] + b0v;
            float v01 = acc[i][j][1] + b1v;
            float v10 = acc[i][j][2] + b0v;
            float v11 = acc[i][j][3] + b1v;
            float2 lo; lo.x = v00; lo.y = v01;
            float2 hi; hi.x = v10; hi.y = v11;
            *(float2*)&Cout[(size_t)row * C + cg] = lo;
            *(float2*)&Cout[(size_t)(row + 8) * C + cg] = hi;
            s0 += v00 + v10;  s1 += v01 + v11;
            q0 += v00 * v00 + v10 * v10;
            q1 += v01 * v01 + v11 * v11;
        }
        atomicAdd(&ssum[cl], s0);     atomicAdd(&ssum[cl + 1], s1);
        atomicAdd(&sssq[cl], q0);     atomicAdd(&sssq[cl + 1], q1);
    }
    __syncthreads();
    if (tid < 128) {
        atomicAdd(&sum[n0 + tid], ssum[tid]);
        atomicAdd(&ssq[n0 + tid], sssq[tid]);
    }
}

// ---------------------------------------------------------------------------
extern "C" void kernel_launch(void* const* d_in, const int* in_sizes, int n_in,
                              void* d_out, int out_size)
{
    const float* feat    = (const float*)d_in[0];
    const float* skip    = (const float*)d_in[1];
    const int*   cluster = (const int*)  d_in[2];
    const float* W_proj  = (const float*)d_in[3];
    const float* b_proj  = (const float*)d_in[4];
    const float* gamma_p = (const float*)d_in[5];
    const float* beta_p  = (const float*)d_in[6];
    const float* W_skip  = (const float*)d_in[7];
    const float* b_skip  = (const float*)d_in[8];
    const float* gamma_s = (const float*)d_in[9];
    const float* beta_s  = (const float*)d_in[10];
    float* out = (float*)d_out;

    float *h_ptr, *s_ptr, *sum_p, *ssq_p, *sum_s, *ssq_s;
    __half *wtp, *wts;
    cudaGetSymbolAddress((void**)&h_ptr, g_h);
    cudaGetSymbolAddress((void**)&s_ptr, g_s);
    cudaGetSymbolAddress((void**)&wtp, g_wt_proj);
    cudaGetSymbolAddress((void**)&wts, g_wt_skip);
    cudaGetSymbolAddress((void**)&sum_p, g_sum_p);
    cudaGetSymbolAddress((void**)&ssq_p, g_ssq_p);
    cudaGetSymbolAddress((void**)&sum_s, g_sum_s);
    cudaGetSymbolAddress((void**)&ssq_s, g_ssq_s);

    cudaFuncSetAttribute(mma_gemm_kernel,
                         cudaFuncAttributeMaxDynamicSharedMemorySize, SMEM_BYTES);

    zero_stats_kernel<<<1, 256>>>();

    transpose_w_kernel<<<dim3(256 / 32, 512 / 32), dim3(32, 8)>>>(W_proj, wtp, 512, 256);
    transpose_w_kernel<<<dim3(256 / 32, 256 / 32), dim3(32, 8)>>>(W_skip, wts, 256, 256);

    // GEMM2 first (big, fp32 skip read directly), then GEMM1 (fp32 feat).
    mma_gemm_kernel<<<dim3(2, N_OUT / 128), 256, SMEM_BYTES>>>(
        skip, wts, b_skip, s_ptr, 256, sum_s, ssq_s);

    mma_gemm_kernel<<<dim3(2, N_IN / 128), 256, SMEM_BYTES>>>(
        feat, wtp, b_proj, h_ptr, 512, sum_p, ssq_p);

    finalize_kernel<<<1, 256>>>(gamma_p, beta_p, gamma_s, beta_s);

    fuse_out_kernel<<<(N_OUT * 64) / 256, 256>>>(cluster, out);
}

// round 14
// speedup vs baseline: 1.0003x; 1.0003x over previous
#include <cuda_runtime.h>
#include <cuda_fp16.h>
#include <cstdint>

// ---------------------------------------------------------------------------
// UnpoolWithSkip — R14: heterogeneous-grid overlap.
//  K1 transpose weights (tiny, sequential — GEMM2 needs wts)
//  K2 combined: bid0 = zero stats | bids 1..128 = f2h(feat) grid-stride |
//               bids 129.. = GEMM2 tiles (R13 fp32-A body, no f2h(skip))
//      -> conversion + zeroing hidden under compute-bound GEMM2.
//  K3 GEMM1 (R12 fp16-A ldmatrix body, feat_h produced by K2)
//  K4 finalize, K5 fuse (fp32).
// ---------------------------------------------------------------------------

#define EPS 1e-5f

static constexpr int N_IN  = 65536;
static constexpr int N_OUT = 262144;
static constexpr int C     = 256;

static constexpr int F2H_CTAS  = 128;
static constexpr int GEMM2_BID0 = 1 + F2H_CTAS;              // 129
static constexpr int NCTA2 = (N_OUT / 128) * 2;              // 4096

__device__ float  g_h[(size_t)N_IN  * C];
__device__ float  g_s[(size_t)N_OUT * C];
__device__ __half g_feat_h[(size_t)N_IN  * 512];
__device__ __half g_wt_proj[(size_t)C * 512];
__device__ __half g_wt_skip[(size_t)C * 256];
__device__ float g_sum_p[C], g_ssq_p[C];
__device__ float g_sum_s[C], g_ssq_s[C];
__device__ float g_a_p[C], g_b_p[C];
__device__ float g_a_s[C], g_b_s[C];

// ---------------------------------------------------------------------------
__device__ __forceinline__ void mma_f16(float* c, const uint32_t* a, const uint32_t* b) {
    asm volatile(
        "mma.sync.aligned.m16n8k16.row.col.f32.f16.f16.f32 "
        "{%0,%1,%2,%3}, {%4,%5,%6,%7}, {%8,%9}, {%0,%1,%2,%3};"
        : "+f"(c[0]), "+f"(c[1]), "+f"(c[2]), "+f"(c[3])
        : "r"(a[0]), "r"(a[1]), "r"(a[2]), "r"(a[3]), "r"(b[0]), "r"(b[1]));
}
__device__ __forceinline__ void ldsm_x4(uint32_t& d0, uint32_t& d1,
                                        uint32_t& d2, uint32_t& d3, uint32_t addr) {
    asm volatile("ldmatrix.sync.aligned.m8n8.x4.shared.b16 {%0,%1,%2,%3}, [%4];"
                 : "=r"(d0), "=r"(d1), "=r"(d2), "=r"(d3) : "r"(addr));
}
__device__ __forceinline__ uint32_t smem_u32(const void* p) {
    uint32_t a;
    asm("{ .reg .u64 t; cvta.to.shared.u64 t, %1; cvt.u32.u64 %0, t; }"
        : "=r"(a) : "l"(p));
    return a;
}
__device__ __forceinline__ uint32_t pack_h2(float2 v) {
    __half2 h = __floats2half2_rn(v.x, v.y);
    return *(uint32_t*)&h;
}

// ---------------------------------------------------------------------------
__global__ void transpose_w_kernel(const float* __restrict__ W,
                                   __half* __restrict__ Wt, int K, int N) {
    __shared__ float t[32][33];
    int n0 = blockIdx.x * 32, k0 = blockIdx.y * 32;
    int tx = threadIdx.x, ty = threadIdx.y;
    #pragma unroll
    for (int i = 0; i < 32; i += 8)
        t[ty + i][tx] = W[(size_t)(k0 + ty + i) * N + n0 + tx];
    __syncthreads();
    #pragma unroll
    for (int i = 0; i < 32; i += 8)
        Wt[(size_t)(n0 + ty + i) * K + k0 + tx] = __float2half_rn(t[tx][ty + i]);
}

__global__ void finalize_kernel(
    const float* __restrict__ gamma_p, const float* __restrict__ beta_p,
    const float* __restrict__ gamma_s, const float* __restrict__ beta_s)
{
    int c = threadIdx.x;
    {
        float m = g_sum_p[c] * (1.f / N_IN);
        float v = g_ssq_p[c] * (1.f / N_IN) - m * m;
        float a = gamma_p[c] * rsqrtf(v + EPS);
        g_a_p[c] = a; g_b_p[c] = beta_p[c] - m * a;
    }
    {
        float m = g_sum_s[c] * (1.f / N_OUT);
        float v = g_ssq_s[c] * (1.f / N_OUT) - m * m;
        float a = gamma_s[c] * rsqrtf(v + EPS);
        g_a_s[c] = a; g_b_s[c] = beta_s[c] - m * a;
    }
}

__global__ __launch_bounds__(256) void fuse_out_kernel(
    const int* __restrict__ cluster, float* __restrict__ out)
{
    int idx = blockIdx.x * 256 + threadIdx.x;
    int n  = idx >> 6;
    int c4 = (idx & 63) << 2;
    int k  = __ldg(&cluster[n]);

    float4 h  = *(const float4*)&g_h[(size_t)k * C + c4];
    float4 sv = *(const float4*)&g_s[(size_t)n * C + c4];
    float4 ap = *(const float4*)&g_a_p[c4];
    float4 bp = *(const float4*)&g_b_p[c4];
    float4 as_ = *(const float4*)&g_a_s[c4];
    float4 bs_ = *(const float4*)&g_b_s[c4];

    float4 o;
    o.x = fmaxf(fmaf(ap.x, h.x, bp.x), 0.f) + fmaxf(fmaf(as_.x, sv.x, bs_.x), 0.f);
    o.y = fmaxf(fmaf(ap.y, h.y, bp.y), 0.f) + fmaxf(fmaf(as_.y, sv.y, bs_.y), 0.f);
    o.z = fmaxf(fmaf(ap.z, h.z, bp.z), 0.f) + fmaxf(fmaf(as_.z, sv.z, bs_.z), 0.f);
    o.w = fmaxf(fmaf(ap.w, h.w, bp.w), 0.f) + fmaxf(fmaf(as_.w, sv.w, bs_.w), 0.f);
    *(float4*)&out[(size_t)n * C + c4] = o;
}

// ---------------------------------------------------------------------------
// Combined kernel: zero-stats + f2h(feat) + GEMM2 (fp32 A direct, R13 body).
// GEMM2: g_s[M,256] = skip[M,256] @ wts[256,256]^T + b_skip, fp32 acc/out,
// fused per-channel fp32 sum/sumsq. Tile 128x128, BK=64, 2-stage cp.async.
// ---------------------------------------------------------------------------
static constexpr int A_PADF   = 68;
static constexpr int A_ROWB   = A_PADF * 4;                // 272 B
static constexpr uint32_t A_SB = 128u * A_ROWB;            // 34816 B
static constexpr int B_PADH   = 72;
static constexpr int B_ROWB   = B_PADH * 2;                // 144 B
static constexpr uint32_t BB  = 128u * B_ROWB;             // 18432 B
static constexpr uint32_t ST_F32 = A_SB + BB;              // 53248 B
static constexpr uint32_t SMEM_F32 = ST_F32 * 2;           // 106496 B

__device__ __forceinline__ void load_tile_f32(
    const float* __restrict__ A, const __half* __restrict__ Bt, int K,
    int m0, int n0, int kt, uint32_t sbase, int tid)
{
    #pragma unroll
    for (int p = 0; p < 8; p++) {
        int idx = tid + p * 256;
        int row = idx >> 4, ch = idx & 15;
        const float* ga = A + (size_t)(m0 + row) * K + kt * 64 + ch * 4;
        uint32_t sa = sbase + row * A_ROWB + ch * 16;
        asm volatile("cp.async.cg.shared.global [%0], [%1], 16;"
                     :: "r"(sa), "l"(ga) : "memory");
    }
    #pragma unroll
    for (int p = 0; p < 4; p++) {
        int idx = tid + p * 256;
        int row = idx >> 3, ch = idx & 7;
        const __half* gb = Bt + (size_t)(n0 + row) * K + kt * 64 + ch * 8;
        uint32_t sb = sbase + A_SB + row * B_ROWB + ch * 16;
        asm volatile("cp.async.cg.shared.global [%0], [%1], 16;"
                     :: "r"(sb), "l"(gb) : "memory");
    }
    asm volatile("cp.async.commit_group;" ::: "memory");
}

__global__ __launch_bounds__(256, 2) void combined_kernel(
    const float* __restrict__ skip, const __half* __restrict__ wts,
    const float* __restrict__ b_skip,
    const float* __restrict__ feat)
{
    const int bid = blockIdx.x;
    const int tid = threadIdx.x;

    if (bid == 0) {                      // zero all stats
        g_sum_p[tid] = 0.f; g_ssq_p[tid] = 0.f;
        g_sum_s[tid] = 0.f; g_ssq_s[tid] = 0.f;
        return;
    }
    if (bid < GEMM2_BID0) {              // f2h(feat): grid-stride, 8 elems/thr
        const size_t total8 = (size_t)N_IN * 512 / 8;     // 4,194,304
        const size_t stride = (size_t)F2H_CTAS * 256;
        for (size_t i = (size_t)(bid - 1) * 256 + tid; i < total8; i += stride) {
            size_t e = i * 8;
            float4 a = *(const float4*)(feat + e);
            float4 b = *(const float4*)(feat + e + 4);
            __half2 h[4];
            h[0] = __floats2half2_rn(a.x, a.y);
            h[1] = __floats2half2_rn(a.z, a.w);
            h[2] = __floats2half2_rn(b.x, b.y);
            h[3] = __floats2half2_rn(b.z, b.w);
            *(uint4*)(g_feat_h + e) = *(uint4*)h;
        }
        return;
    }

    // ---------------- GEMM2 tile (R13 fp32-A body) ----------------
    extern __shared__ char smem_raw[];
    __shared__ float ssum[128], sssq[128];

    const int b  = bid - GEMM2_BID0;
    const int n0 = (b & 1) * 128;
    const int m0 = (b >> 1) * 128;
    const int K  = 256;

    const int lane = tid & 31;
    const int wid  = tid >> 5;
    const int wm   = wid & 3;
    const int wn   = wid >> 2;
    const int g    = lane >> 2;
    const int t    = lane & 3;

    const uint32_t sbase = smem_u32(smem_raw);

    if (tid < 128) { ssum[tid] = 0.f; sssq[tid] = 0.f; }

    float acc[2][8][4];
    #pragma unroll
    for (int i = 0; i < 2; i++)
        #pragma unroll
        for (int j = 0; j < 8; j++)
            #pragma unroll
            for (int q = 0; q < 4; q++) acc[i][j][q] = 0.f;

    const int KT = K >> 6;
    const int mw = wm * 32;
    const int nw = wn * 64;

    const int lm = lane >> 3;
    const int lr = lane & 7;
    uint32_t b_off[4];
    #pragma unroll
    for (int p = 0; p < 4; p++)
        b_off[p] = A_SB
                 + (uint32_t)((nw + 16 * p + 8 * (lm >> 1) + lr) * B_ROWB
                              + (lm & 1) * 16);

    load_tile_f32(skip, wts, K, m0, n0, 0, sbase, tid);

    int buf = 0;
    for (int kt = 0; kt < KT; kt++) {
        if (kt + 1 < KT) {
            load_tile_f32(skip, wts, K, m0, n0, kt + 1,
                          sbase + (uint32_t)(buf ^ 1) * ST_F32, tid);
            asm volatile("cp.async.wait_group 1;" ::: "memory");
        } else {
            asm volatile("cp.async.wait_group 0;" ::: "memory");
        }
        __syncthreads();

        const uint32_t stg = sbase + (uint32_t)buf * ST_F32;
        const float2* Af = (const float2*)(smem_raw + (size_t)buf * ST_F32);

        #pragma unroll
        for (int ks = 0; ks < 4; ks++) {
            const int kf2 = ks * 8 + t;
            uint32_t af[2][4];
            #pragma unroll
            for (int i = 0; i < 2; i++) {
                const int r0 = (mw + i * 16 + g) * (A_PADF / 2);
                const int r1 = r0 + 8 * (A_PADF / 2);
                af[i][0] = pack_h2(Af[r0 + kf2]);
                af[i][1] = pack_h2(Af[r1 + kf2]);
                af[i][2] = pack_h2(Af[r0 + kf2 + 4]);
                af[i][3] = pack_h2(Af[r1 + kf2 + 4]);
            }
            const uint32_t kb = ks * 32;
            uint32_t bf[8][2];
            #pragma unroll
            for (int p = 0; p < 4; p++)
                ldsm_x4(bf[2*p][0], bf[2*p][1], bf[2*p+1][0], bf[2*p+1][1],
                        stg + b_off[p] + kb);
            #pragma unroll
            for (int i = 0; i < 2; i++)
                #pragma unroll
                for (int j = 0; j < 8; j++)
                    mma_f16(acc[i][j], af[i], bf[j]);
        }
        __syncthreads();
        buf ^= 1;
    }

    #pragma unroll
    for (int j = 0; j < 8; j++) {
        const int cl = nw + j * 8 + 2 * t;
        const int cg = n0 + cl;
        const float b0v = __ldg(&b_skip[cg]);
        const float b1v = __ldg(&b_skip[cg + 1]);
        float s0 = 0.f, s1 = 0.f, q0 = 0.f, q1 = 0.f;
        #pragma unroll
        for (int i = 0; i < 2; i++) {
            const int row = m0 + mw + i * 16 + g;
            float v00 = acc[i][j][0] + b0v;
            float v01 = acc[i][j][1] + b1v;
            float v10 = acc[i][j][2] + b0v;
            float v11 = acc[i][j][3] + b1v;
            float2 lo; lo.x = v00; lo.y = v01;
            float2 hi; hi.x = v10; hi.y = v11;
            *(float2*)&g_s[(size_t)row * C + cg] = lo;
            *(float2*)&g_s[(size_t)(row + 8) * C + cg] = hi;
            s0 += v00 + v10;  s1 += v01 + v11;
            q0 += v00 * v00 + v10 * v10;
            q1 += v01 * v01 + v11 * v11;
        }
        atomicAdd(&ssum[cl], s0);     atomicAdd(&ssum[cl + 1], s1);
        atomicAdd(&sssq[cl], q0);     atomicAdd(&sssq[cl + 1], q1);
    }
    __syncthreads();
    if (tid < 128) {
        atomicAdd(&g_sum_s[n0 + tid], ssum[tid]);
        atomicAdd(&g_ssq_s[n0 + tid], sssq[tid]);
    }
}

// ---------------------------------------------------------------------------
// GEMM1 (R12 body): g_h = feat_h @ wtp^T + b_proj. fp16 A via ldmatrix,
// 3-stage cp.async, fp32 out + stats. Grid (2, 512).
// ---------------------------------------------------------------------------
static constexpr int H_PADH  = 72;
static constexpr int H_ROWB  = H_PADH * 2;                 // 144
static constexpr uint32_t H_AB = 128u * H_ROWB;            // 18432
static constexpr uint32_t ST_H = H_AB * 2;                 // 36864
static constexpr int H_STAGES = 3;
static constexpr uint32_t SMEM_H = ST_H * H_STAGES;        // 110592

__device__ __forceinline__ void load_tile_h16(
    const __half* __restrict__ A, const __half* __restrict__ Bt, int K,
    int m0, int n0, int kt, uint32_t sbase, int tid)
{
    #pragma unroll
    for (int p = 0; p < 4; p++) {
        int idx = tid + p * 256;
        int row = idx >> 3, ch = idx & 7;
        const __half* ga = A + (size_t)(m0 + row) * K + kt * 64 + ch * 8;
        uint32_t sa = sbase + row * H_ROWB + ch * 16;
        asm volatile("cp.async.cg.shared.global [%0], [%1], 16;"
                     :: "r"(sa), "l"(ga) : "memory");
        const __half* gb = Bt + (size_t)(n0 + row) * K + kt * 64 + ch * 8;
        uint32_t sb = sbase + H_AB + row * H_ROWB + ch * 16;
        asm volatile("cp.async.cg.shared.global [%0], [%1], 16;"
                     :: "r"(sb), "l"(gb) : "memory");
    }
    asm volatile("cp.async.commit_group;" ::: "memory");
}

__global__ __launch_bounds__(256) void gemm1_kernel(
    const __half* __restrict__ A, const __half* __restrict__ Bt,
    const float* __restrict__ bias, float* __restrict__ Cout,
    int K, float* __restrict__ sum, float* __restrict__ ssq)
{
    extern __shared__ char smem_raw[];
    __shared__ float ssum[128], sssq[128];

    const int tid  = threadIdx.x;
    const int lane = tid & 31;
    const int wid  = tid >> 5;
    const int wm   = wid & 3;
    const int wn   = wid >> 2;
    const int g    = lane >> 2;
    const int t    = lane & 3;

    const int n0 = blockIdx.x * 128;
    const int m0 = blockIdx.y * 128;

    const uint32_t sbase = smem_u32(smem_raw);

    if (tid < 128) { ssum[tid] = 0.f; sssq[tid] = 0.f; }

    float acc[2][8][4];
    #pragma unroll
    for (int i = 0; i < 2; i++)
        #pragma unroll
        for (int j = 0; j < 8; j++)
            #pragma unroll
            for (int q = 0; q < 4; q++) acc[i][j][q] = 0.f;

    const int KT = K >> 6;
    const int mw = wm * 32;
    const int nw = wn * 64;

    const int lm = lane >> 3;
    const int lr = lane & 7;
    uint32_t a_off[2];
    #pragma unroll
    for (int i = 0; i < 2; i++)
        a_off[i] = (uint32_t)((mw + i * 16 + (lm & 1) * 8 + lr) * H_ROWB
                              + (lm >> 1) * 16);
    uint32_t b_off[4];
    #pragma unroll
    for (int p = 0; p < 4; p++)
        b_off[p] = H_AB
                 + (uint32_t)((nw + 16 * p + 8 * (lm >> 1) + lr) * H_ROWB
                              + (lm & 1) * 16);

    load_tile_h16(A, Bt, K, m0, n0, 0, sbase, tid);
    load_tile_h16(A, Bt, K, m0, n0, 1, sbase + ST_H, tid);

    int buf = 0;
    for (int kt = 0; kt < KT; kt++) {
        if (kt >= KT - 2)
            asm volatile("cp.async.wait_group 0;" ::: "memory");
        else
            asm volatile("cp.async.wait_group 1;" ::: "memory");
        __syncthreads();

        if (kt + 2 < KT) {
            int nb = buf + 2; if (nb >= H_STAGES) nb -= H_STAGES;
            load_tile_h16(A, Bt, K, m0, n0, kt + 2,
                          sbase + (uint32_t)nb * ST_H, tid);
        }

        const uint32_t stg = sbase + (uint32_t)buf * ST_H;

        #pragma unroll
        for (int ks = 0; ks < 4; ks++) {
            const uint32_t kb = ks * 32;
            uint32_t af[2][4];
            ldsm_x4(af[0][0], af[0][1], af[0][2], af[0][3], stg + a_off[0] + kb);
            ldsm_x4(af[1][0], af[1][1], af[1][2], af[1][3], stg + a_off[1] + kb);
            uint32_t bf[8][2];
            #pragma unroll
            for (int p = 0; p < 4; p++)
                ldsm_x4(bf[2*p][0], bf[2*p][1], bf[2*p+1][0], bf[2*p+1][1],
                        stg + b_off[p] + kb);
            #pragma unroll
            for (int i = 0; i < 2; i++)
                #pragma unroll
                for (int j = 0; j < 8; j++)
                    mma_f16(acc[i][j], af[i], bf[j]);
        }

        buf++; if (buf == H_STAGES) buf = 0;
    }
    __syncthreads();

    #pragma unroll
    for (int j = 0; j < 8; j++) {
        const int cl = nw + j * 8 + 2 * t;
        const int cg = n0 + cl;
        const float b0v = __ldg(&bias[cg]);
        const float b1v = __ldg(&bias[cg + 1]);
        float s0 = 0.f, s1 = 0.f, q0 = 0.f, q1 = 0.f;
        #pragma unroll
        for (int i = 0; i < 2; i++) {
            const int row = m0 + mw + i * 16 + g;
            float v00 = acc[i][j][0] + b0v;
            float v01 = acc[i][j][1] + b1v;
            float v10 = acc[i][j][2] + b0v;
            float v11 = acc[i][j][3] + b1v;
            float2 lo; lo.x = v00; lo.y = v01;
            float2 hi; hi.x = v10; hi.y = v11;
            *(float2*)&Cout[(size_t)row * C + cg] = lo;
            *(float2*)&Cout[(size_t)(row + 8) * C + cg] = hi;
            s0 += v00 + v10;  s1 += v01 + v11;
            q0 += v00 * v00 + v10 * v10;
            q1 += v01 * v01 + v11 * v11;
        }
        atomicAdd(&ssum[cl], s0);     atomicAdd(&ssum[cl + 1], s1);
        atomicAdd(&sssq[cl], q0);     atomicAdd(&sssq[cl + 1], q1);
    }
    __syncthreads();
    if (tid < 128) {
        atomicAdd(&sum[n0 + tid], ssum[tid]);
        atomicAdd(&ssq[n0 + tid], sssq[tid]);
    }
}

// ---------------------------------------------------------------------------
extern "C" void kernel_launch(void* const* d_in, const int* in_sizes, int n_in,
                              void* d_out, int out_size)
{
    const float* feat    = (const float*)d_in[0];
    const float* skip    = (const float*)d_in[1];
    const int*   cluster = (const int*)  d_in[2];
    const float* W_proj  = (const float*)d_in[3];
    const float* b_proj  = (const float*)d_in[4];
    const float* gamma_p = (const float*)d_in[5];
    const float* beta_p  = (const float*)d_in[6];
    const float* W_skip  = (const float*)d_in[7];
    const float* b_skip  = (const float*)d_in[8];
    const float* gamma_s = (const float*)d_in[9];
    const float* beta_s  = (const float*)d_in[10];
    float* out = (float*)d_out;

    float *h_ptr, *sum_p, *ssq_p;
    __half *feat_h, *wtp, *wts;
    cudaGetSymbolAddress((void**)&h_ptr, g_h);
    cudaGetSymbolAddress((void**)&feat_h, g_feat_h);
    cudaGetSymbolAddress((void**)&wtp, g_wt_proj);
    cudaGetSymbolAddress((void**)&wts, g_wt_skip);
    cudaGetSymbolAddress((void**)&sum_p, g_sum_p);
    cudaGetSymbolAddress((void**)&ssq_p, g_ssq_p);

    cudaFuncSetAttribute(combined_kernel,
                         cudaFuncAttributeMaxDynamicSharedMemorySize, SMEM_F32);
    cudaFuncSetAttribute(gemm1_kernel,
                         cudaFuncAttributeMaxDynamicSharedMemorySize, SMEM_H);

    // Tiny sequential transposes (GEMM2 needs wts before any tile starts).
    transpose_w_kernel<<<dim3(256 / 32, 512 / 32), dim3(32, 8)>>>(W_proj, wtp, 512, 256);
    transpose_w_kernel<<<dim3(256 / 32, 256 / 32), dim3(32, 8)>>>(W_skip, wts, 256, 256);

    // Combined: zero stats + f2h(feat) hidden under GEMM2 (fp32 skip direct).
    combined_kernel<<<GEMM2_BID0 + NCTA2, 256, SMEM_F32>>>(
        skip, wts, b_skip, feat);

    // GEMM1 on converted feat_h (fast fp16 path).
    gemm1_kernel<<<dim3(2, N_IN / 128), 256, SMEM_H>>>(
        feat_h, wtp, b_proj, h_ptr, 512, sum_p, ssq_p);

    finalize_kernel<<<1, 256>>>(gamma_p, beta_p, gamma_s, beta_s);

    fuse_out_kernel<<<(N_OUT * 64) / 256, 256>>>(cluster, out);
}

// round 15
// speedup vs baseline: 1.0089x; 1.0086x over previous
#include <cuda_runtime.h>
#include <cuda_fp16.h>
#include <cstdint>

// ---------------------------------------------------------------------------
// UnpoolWithSkip — R15: arithmetically-optimal sequential pipeline.
//  K0 zero stats
//  K1 transpose weights to fp16 (tiny)
//  K2 f2h(feat) only (28us; skip conversion dropped entirely)
//  K3 GEMM2: g_s = skip(fp32, direct) @ wts^T + b_skip   [R13 fp32-A body]
//  K4 GEMM1: g_h = feat_h(fp16) @ wtp^T + b_proj         [R12 fp16 body]
//  K5 finalize (BN affine)
//  K6 fuse (fp32 scratch, fp32 out)
// No heterogeneous packing, no fp16 scratch — both measured as regressions.
// ---------------------------------------------------------------------------

#define EPS 1e-5f

static constexpr int N_IN  = 65536;
static constexpr int N_OUT = 262144;
static constexpr int C     = 256;

__device__ float  g_h[(size_t)N_IN  * C];
__device__ float  g_s[(size_t)N_OUT * C];
__device__ __half g_feat_h[(size_t)N_IN  * 512];
__device__ __half g_wt_proj[(size_t)C * 512];
__device__ __half g_wt_skip[(size_t)C * 256];
__device__ float g_sum_p[C], g_ssq_p[C];
__device__ float g_sum_s[C], g_ssq_s[C];
__device__ float g_a_p[C], g_b_p[C];
__device__ float g_a_s[C], g_b_s[C];

// ---------------------------------------------------------------------------
__device__ __forceinline__ void mma_f16(float* c, const uint32_t* a, const uint32_t* b) {
    asm volatile(
        "mma.sync.aligned.m16n8k16.row.col.f32.f16.f16.f32 "
        "{%0,%1,%2,%3}, {%4,%5,%6,%7}, {%8,%9}, {%0,%1,%2,%3};"
        : "+f"(c[0]), "+f"(c[1]), "+f"(c[2]), "+f"(c[3])
        : "r"(a[0]), "r"(a[1]), "r"(a[2]), "r"(a[3]), "r"(b[0]), "r"(b[1]));
}
__device__ __forceinline__ void ldsm_x4(uint32_t& d0, uint32_t& d1,
                                        uint32_t& d2, uint32_t& d3, uint32_t addr) {
    asm volatile("ldmatrix.sync.aligned.m8n8.x4.shared.b16 {%0,%1,%2,%3}, [%4];"
                 : "=r"(d0), "=r"(d1), "=r"(d2), "=r"(d3) : "r"(addr));
}
__device__ __forceinline__ uint32_t smem_u32(const void* p) {
    uint32_t a;
    asm("{ .reg .u64 t; cvta.to.shared.u64 t, %1; cvt.u32.u64 %0, t; }"
        : "=r"(a) : "l"(p));
    return a;
}
__device__ __forceinline__ uint32_t pack_h2(float2 v) {
    __half2 h = __floats2half2_rn(v.x, v.y);
    return *(uint32_t*)&h;
}

// ---------------------------------------------------------------------------
__global__ void zero_stats_kernel() {
    int c = threadIdx.x;
    g_sum_p[c] = 0.f; g_ssq_p[c] = 0.f;
    g_sum_s[c] = 0.f; g_ssq_s[c] = 0.f;
}

__global__ __launch_bounds__(256) void f2h_kernel(
    const float* __restrict__ src, __half* __restrict__ dst)
{
    size_t i = ((size_t)blockIdx.x * 256 + threadIdx.x) * 8;
    float4 a = *(const float4*)(src + i);
    float4 b = *(const float4*)(src + i + 4);
    __half2 h[4];
    h[0] = __floats2half2_rn(a.x, a.y);
    h[1] = __floats2half2_rn(a.z, a.w);
    h[2] = __floats2half2_rn(b.x, b.y);
    h[3] = __floats2half2_rn(b.z, b.w);
    *(uint4*)(dst + i) = *(uint4*)h;
}

__global__ void transpose_w_kernel(const float* __restrict__ W,
                                   __half* __restrict__ Wt, int K, int N) {
    __shared__ float t[32][33];
    int n0 = blockIdx.x * 32, k0 = blockIdx.y * 32;
    int tx = threadIdx.x, ty = threadIdx.y;
    #pragma unroll
    for (int i = 0; i < 32; i += 8)
        t[ty + i][tx] = W[(size_t)(k0 + ty + i) * N + n0 + tx];
    __syncthreads();
    #pragma unroll
    for (int i = 0; i < 32; i += 8)
        Wt[(size_t)(n0 + ty + i) * K + k0 + tx] = __float2half_rn(t[tx][ty + i]);
}

__global__ void finalize_kernel(
    const float* __restrict__ gamma_p, const float* __restrict__ beta_p,
    const float* __restrict__ gamma_s, const float* __restrict__ beta_s)
{
    int c = threadIdx.x;
    {
        float m = g_sum_p[c] * (1.f / N_IN);
        float v = g_ssq_p[c] * (1.f / N_IN) - m * m;
        float a = gamma_p[c] * rsqrtf(v + EPS);
        g_a_p[c] = a; g_b_p[c] = beta_p[c] - m * a;
    }
    {
        float m = g_sum_s[c] * (1.f / N_OUT);
        float v = g_ssq_s[c] * (1.f / N_OUT) - m * m;
        float a = gamma_s[c] * rsqrtf(v + EPS);
        g_a_s[c] = a; g_b_s[c] = beta_s[c] - m * a;
    }
}

__global__ __launch_bounds__(256) void fuse_out_kernel(
    const int* __restrict__ cluster, float* __restrict__ out)
{
    int idx = blockIdx.x * 256 + threadIdx.x;
    int n  = idx >> 6;
    int c4 = (idx & 63) << 2;
    int k  = __ldg(&cluster[n]);

    float4 h  = *(const float4*)&g_h[(size_t)k * C + c4];
    float4 sv = *(const float4*)&g_s[(size_t)n * C + c4];
    float4 ap = *(const float4*)&g_a_p[c4];
    float4 bp = *(const float4*)&g_b_p[c4];
    float4 as_ = *(const float4*)&g_a_s[c4];
    float4 bs_ = *(const float4*)&g_b_s[c4];

    float4 o;
    o.x = fmaxf(fmaf(ap.x, h.x, bp.x), 0.f) + fmaxf(fmaf(as_.x, sv.x, bs_.x), 0.f);
    o.y = fmaxf(fmaf(ap.y, h.y, bp.y), 0.f) + fmaxf(fmaf(as_.y, sv.y, bs_.y), 0.f);
    o.z = fmaxf(fmaf(ap.z, h.z, bp.z), 0.f) + fmaxf(fmaf(as_.z, sv.z, bs_.z), 0.f);
    o.w = fmaxf(fmaf(ap.w, h.w, bp.w), 0.f) + fmaxf(fmaf(as_.w, sv.w, bs_.w), 0.f);
    *(float4*)&out[(size_t)n * C + c4] = o;
}

// ---------------------------------------------------------------------------
// GEMM2 (R13 body): g_s = skip(fp32) @ wts^T + b_skip. fp32 A in smem,
// consumer converts float2->half2. Tile 128x128, BK=64, 2-stage, grid (2, 2048).
// ---------------------------------------------------------------------------
static constexpr int A_PADF   = 68;
static constexpr int A_ROWB   = A_PADF * 4;                // 272 B
static constexpr uint32_t A_SB = 128u * A_ROWB;            // 34816 B
static constexpr int B_PADH   = 72;
static constexpr int B_ROWB   = B_PADH * 2;                // 144 B
static constexpr uint32_t BB  = 128u * B_ROWB;             // 18432 B
static constexpr uint32_t ST_F32 = A_SB + BB;              // 53248 B
static constexpr uint32_t SMEM_F32 = ST_F32 * 2;           // 106496 B

__device__ __forceinline__ void load_tile_f32(
    const float* __restrict__ A, const __half* __restrict__ Bt, int K,
    int m0, int n0, int kt, uint32_t sbase, int tid)
{
    #pragma unroll
    for (int p = 0; p < 8; p++) {
        int idx = tid + p * 256;
        int row = idx >> 4, ch = idx & 15;
        const float* ga = A + (size_t)(m0 + row) * K + kt * 64 + ch * 4;
        uint32_t sa = sbase + row * A_ROWB + ch * 16;
        asm volatile("cp.async.cg.shared.global [%0], [%1], 16;"
                     :: "r"(sa), "l"(ga) : "memory");
    }
    #pragma unroll
    for (int p = 0; p < 4; p++) {
        int idx = tid + p * 256;
        int row = idx >> 3, ch = idx & 7;
        const __half* gb = Bt + (size_t)(n0 + row) * K + kt * 64 + ch * 8;
        uint32_t sb = sbase + A_SB + row * B_ROWB + ch * 16;
        asm volatile("cp.async.cg.shared.global [%0], [%1], 16;"
                     :: "r"(sb), "l"(gb) : "memory");
    }
    asm volatile("cp.async.commit_group;" ::: "memory");
}

__global__ __launch_bounds__(256) void gemm2_kernel(
    const float* __restrict__ A, const __half* __restrict__ Bt,
    const float* __restrict__ bias, float* __restrict__ Cout,
    float* __restrict__ sum, float* __restrict__ ssq)
{
    extern __shared__ char smem_raw[];
    __shared__ float ssum[128], sssq[128];

    const int tid  = threadIdx.x;
    const int lane = tid & 31;
    const int wid  = tid >> 5;
    const int wm   = wid & 3;
    const int wn   = wid >> 2;
    const int g    = lane >> 2;
    const int t    = lane & 3;

    const int n0 = blockIdx.x * 128;
    const int m0 = blockIdx.y * 128;
    const int K  = 256;

    const uint32_t sbase = smem_u32(smem_raw);

    if (tid < 128) { ssum[tid] = 0.f; sssq[tid] = 0.f; }

    float acc[2][8][4];
    #pragma unroll
    for (int i = 0; i < 2; i++)
        #pragma unroll
        for (int j = 0; j < 8; j++)
            #pragma unroll
            for (int q = 0; q < 4; q++) acc[i][j][q] = 0.f;

    const int KT = K >> 6;
    const int mw = wm * 32;
    const int nw = wn * 64;

    const int lm = lane >> 3;
    const int lr = lane & 7;
    uint32_t b_off[4];
    #pragma unroll
    for (int p = 0; p < 4; p++)
        b_off[p] = A_SB
                 + (uint32_t)((nw + 16 * p + 8 * (lm >> 1) + lr) * B_ROWB
                              + (lm & 1) * 16);

    load_tile_f32(A, Bt, K, m0, n0, 0, sbase, tid);

    int buf = 0;
    for (int kt = 0; kt < KT; kt++) {
        if (kt + 1 < KT) {
            load_tile_f32(A, Bt, K, m0, n0, kt + 1,
                          sbase + (uint32_t)(buf ^ 1) * ST_F32, tid);
            asm volatile("cp.async.wait_group 1;" ::: "memory");
        } else {
            asm volatile("cp.async.wait_group 0;" ::: "memory");
        }
        __syncthreads();

        const uint32_t stg = sbase + (uint32_t)buf * ST_F32;
        const float2* Af = (const float2*)(smem_raw + (size_t)buf * ST_F32);

        #pragma unroll
        for (int ks = 0; ks < 4; ks++) {
            const int kf2 = ks * 8 + t;
            uint32_t af[2][4];
            #pragma unroll
            for (int i = 0; i < 2; i++) {
                const int r0 = (mw + i * 16 + g) * (A_PADF / 2);
                const int r1 = r0 + 8 * (A_PADF / 2);
                af[i][0] = pack_h2(Af[r0 + kf2]);
                af[i][1] = pack_h2(Af[r1 + kf2]);
                af[i][2] = pack_h2(Af[r0 + kf2 + 4]);
                af[i][3] = pack_h2(Af[r1 + kf2 + 4]);
            }
            const uint32_t kb = ks * 32;
            uint32_t bf[8][2];
            #pragma unroll
            for (int p = 0; p < 4; p++)
                ldsm_x4(bf[2*p][0], bf[2*p][1], bf[2*p+1][0], bf[2*p+1][1],
                        stg + b_off[p] + kb);
            #pragma unroll
            for (int i = 0; i < 2; i++)
                #pragma unroll
                for (int j = 0; j < 8; j++)
                    mma_f16(acc[i][j], af[i], bf[j]);
        }
        __syncthreads();
        buf ^= 1;
    }

    #pragma unroll
    for (int j = 0; j < 8; j++) {
        const int cl = nw + j * 8 + 2 * t;
        const int cg = n0 + cl;
        const float b0v = __ldg(&bias[cg]);
        const float b1v = __ldg(&bias[cg + 1]);
        float s0 = 0.f, s1 = 0.f, q0 = 0.f, q1 = 0.f;
        #pragma unroll
        for (int i = 0; i < 2; i++) {
            const int row = m0 + mw + i * 16 + g;
            float v00 = acc[i][j][0] + b0v;
            float v01 = acc[i][j][1] + b1v;
            float v10 = acc[i][j][2] + b0v;
            float v11 = acc[i][j][3] + b1v;
            float2 lo; lo.x = v00; lo.y = v01;
            float2 hi; hi.x = v10; hi.y = v11;
            *(float2*)&Cout[(size_t)row * C + cg] = lo;
            *(float2*)&Cout[(size_t)(row + 8) * C + cg] = hi;
            s0 += v00 + v10;  s1 += v01 + v11;
            q0 += v00 * v00 + v10 * v10;
            q1 += v01 * v01 + v11 * v11;
        }
        atomicAdd(&ssum[cl], s0);     atomicAdd(&ssum[cl + 1], s1);
        atomicAdd(&sssq[cl], q0);     atomicAdd(&sssq[cl + 1], q1);
    }
    __syncthreads();
    if (tid < 128) {
        atomicAdd(&sum[n0 + tid], ssum[tid]);
        atomicAdd(&ssq[n0 + tid], sssq[tid]);
    }
}

// ---------------------------------------------------------------------------
// GEMM1 (R12 body): g_h = feat_h(fp16) @ wtp^T + b_proj. ldmatrix A+B,
// 3-stage cp.async. Grid (2, 512).
// ---------------------------------------------------------------------------
static constexpr int H_PADH  = 72;
static constexpr int H_ROWB  = H_PADH * 2;                 // 144
static constexpr uint32_t H_AB = 128u * H_ROWB;            // 18432
static constexpr uint32_t ST_H = H_AB * 2;                 // 36864
static constexpr int H_STAGES = 3;
static constexpr uint32_t SMEM_H = ST_H * H_STAGES;        // 110592

__device__ __forceinline__ void load_tile_h16(
    const __half* __restrict__ A, const __half* __restrict__ Bt, int K,
    int m0, int n0, int kt, uint32_t sbase, int tid)
{
    #pragma unroll
    for (int p = 0; p < 4; p++) {
        int idx = tid + p * 256;
        int row = idx >> 3, ch = idx & 7;
        const __half* ga = A + (size_t)(m0 + row) * K + kt * 64 + ch * 8;
        uint32_t sa = sbase + row * H_ROWB + ch * 16;
        asm volatile("cp.async.cg.shared.global [%0], [%1], 16;"
                     :: "r"(sa), "l"(ga) : "memory");
        const __half* gb = Bt + (size_t)(n0 + row) * K + kt * 64 + ch * 8;
        uint32_t sb = sbase + H_AB + row * H_ROWB + ch * 16;
        asm volatile("cp.async.cg.shared.global [%0], [%1], 16;"
                     :: "r"(sb), "l"(gb) : "memory");
    }
    asm volatile("cp.async.commit_group;" ::: "memory");
}

__global__ __launch_bounds__(256) void gemm1_kernel(
    const __half* __restrict__ A, const __half* __restrict__ Bt,
    const float* __restrict__ bias, float* __restrict__ Cout,
    float* __restrict__ sum, float* __restrict__ ssq)
{
    extern __shared__ char smem_raw[];
    __shared__ float ssum[128], sssq[128];

    const int tid  = threadIdx.x;
    const int lane = tid & 31;
    const int wid  = tid >> 5;
    const int wm   = wid & 3;
    const int wn   = wid >> 2;
    const int g    = lane >> 2;
    const int t    = lane & 3;

    const int n0 = blockIdx.x * 128;
    const int m0 = blockIdx.y * 128;
    const int K  = 512;

    const uint32_t sbase = smem_u32(smem_raw);

    if (tid < 128) { ssum[tid] = 0.f; sssq[tid] = 0.f; }

    float acc[2][8][4];
    #pragma unroll
    for (int i = 0; i < 2; i++)
        #pragma unroll
        for (int j = 0; j < 8; j++)
            #pragma unroll
            for (int q = 0; q < 4; q++) acc[i][j][q] = 0.f;

    const int KT = K >> 6;
    const int mw = wm * 32;
    const int nw = wn * 64;

    const int lm = lane >> 3;
    const int lr = lane & 7;
    uint32_t a_off[2];
    #pragma unroll
    for (int i = 0; i < 2; i++)
        a_off[i] = (uint32_t)((mw + i * 16 + (lm & 1) * 8 + lr) * H_ROWB
                              + (lm >> 1) * 16);
    uint32_t b_off[4];
    #pragma unroll
    for (int p = 0; p < 4; p++)
        b_off[p] = H_AB
                 + (uint32_t)((nw + 16 * p + 8 * (lm >> 1) + lr) * H_ROWB
                              + (lm & 1) * 16);

    load_tile_h16(A, Bt, K, m0, n0, 0, sbase, tid);
    load_tile_h16(A, Bt, K, m0, n0, 1, sbase + ST_H, tid);

    int buf = 0;
    for (int kt = 0; kt < KT; kt++) {
        if (kt >= KT - 2)
            asm volatile("cp.async.wait_group 0;" ::: "memory");
        else
            asm volatile("cp.async.wait_group 1;" ::: "memory");
        __syncthreads();

        if (kt + 2 < KT) {
            int nb = buf + 2; if (nb >= H_STAGES) nb -= H_STAGES;
            load_tile_h16(A, Bt, K, m0, n0, kt + 2,
                          sbase + (uint32_t)nb * ST_H, tid);
        }

        const uint32_t stg = sbase + (uint32_t)buf * ST_H;

        #pragma unroll
        for (int ks = 0; ks < 4; ks++) {
            const uint32_t kb = ks * 32;
            uint32_t af[2][4];
            ldsm_x4(af[0][0], af[0][1], af[0][2], af[0][3], stg + a_off[0] + kb);
            ldsm_x4(af[1][0], af[1][1], af[1][2], af[1][3], stg + a_off[1] + kb);
            uint32_t bf[8][2];
            #pragma unroll
            for (int p = 0; p < 4; p++)
                ldsm_x4(bf[2*p][0], bf[2*p][1], bf[2*p+1][0], bf[2*p+1][1],
                        stg + b_off[p] + kb);
            #pragma unroll
            for (int i = 0; i < 2; i++)
                #pragma unroll
                for (int j = 0; j < 8; j++)
                    mma_f16(acc[i][j], af[i], bf[j]);
        }

        buf++; if (buf == H_STAGES) buf = 0;
    }
    __syncthreads();

    #pragma unroll
    for (int j = 0; j < 8; j++) {
        const int cl = nw + j * 8 + 2 * t;
        const int cg = n0 + cl;
        const float b0v = __ldg(&bias[cg]);
        const float b1v = __ldg(&bias[cg + 1]);
        float s0 = 0.f, s1 = 0.f, q0 = 0.f, q1 = 0.f;
        #pragma unroll
        for (int i = 0; i < 2; i++) {
            const int row = m0 + mw + i * 16 + g;
            float v00 = acc[i][j][0] + b0v;
            float v01 = acc[i][j][1] + b1v;
            float v10 = acc[i][j][2] + b0v;
            float v11 = acc[i][j][3] + b1v;
            float2 lo; lo.x = v00; lo.y = v01;
            float2 hi; hi.x = v10; hi.y = v11;
            *(float2*)&Cout[(size_t)row * C + cg] = lo;
            *(float2*)&Cout[(size_t)(row + 8) * C + cg] = hi;
            s0 += v00 + v10;  s1 += v01 + v11;
            q0 += v00 * v00 + v10 * v10;
            q1 += v01 * v01 + v11 * v11;
        }
        atomicAdd(&ssum[cl], s0);     atomicAdd(&ssum[cl + 1], s1);
        atomicAdd(&sssq[cl], q0);     atomicAdd(&sssq[cl + 1], q1);
    }
    __syncthreads();
    if (tid < 128) {
        atomicAdd(&sum[n0 + tid], ssum[tid]);
        atomicAdd(&ssq[n0 + tid], sssq[tid]);
    }
}

// ---------------------------------------------------------------------------
extern "C" void kernel_launch(void* const* d_in, const int* in_sizes, int n_in,
                              void* d_out, int out_size)
{
    const float* feat    = (const float*)d_in[0];
    const float* skip    = (const float*)d_in[1];
    const int*   cluster = (const int*)  d_in[2];
    const float* W_proj  = (const float*)d_in[3];
    const float* b_proj  = (const float*)d_in[4];
    const float* gamma_p = (const float*)d_in[5];
    const float* beta_p  = (const float*)d_in[6];
    const float* W_skip  = (const float*)d_in[7];
    const float* b_skip  = (const float*)d_in[8];
    const float* gamma_s = (const float*)d_in[9];
    const float* beta_s  = (const float*)d_in[10];
    float* out = (float*)d_out;

    float *h_ptr, *s_ptr, *sum_p, *ssq_p, *sum_s, *ssq_s;
    __half *feat_h, *wtp, *wts;
    cudaGetSymbolAddress((void**)&h_ptr, g_h);
    cudaGetSymbolAddress((void**)&s_ptr, g_s);
    cudaGetSymbolAddress((void**)&feat_h, g_feat_h);
    cudaGetSymbolAddress((void**)&wtp, g_wt_proj);
    cudaGetSymbolAddress((void**)&wts, g_wt_skip);
    cudaGetSymbolAddress((void**)&sum_p, g_sum_p);
    cudaGetSymbolAddress((void**)&ssq_p, g_ssq_p);
    cudaGetSymbolAddress((void**)&sum_s, g_sum_s);
    cudaGetSymbolAddress((void**)&ssq_s, g_ssq_s);

    cudaFuncSetAttribute(gemm2_kernel,
                         cudaFuncAttributeMaxDynamicSharedMemorySize, SMEM_F32);
    cudaFuncSetAttribute(gemm1_kernel,
                         cudaFuncAttributeMaxDynamicSharedMemorySize, SMEM_H);

    zero_stats_kernel<<<1, 256>>>();

    transpose_w_kernel<<<dim3(256 / 32, 512 / 32), dim3(32, 8)>>>(W_proj, wtp, 512, 256);
    transpose_w_kernel<<<dim3(256 / 32, 256 / 32), dim3(32, 8)>>>(W_skip, wts, 256, 256);

    // Only feat needs conversion (GEMM2 reads fp32 skip directly).
    f2h_kernel<<<(int)(((size_t)N_IN * 512) / 2048), 256>>>(feat, feat_h);

    // GEMM2 first (big), GEMM1 last so g_h stays L2-warm for the gather.
    gemm2_kernel<<<dim3(2, N_OUT / 128), 256, SMEM_F32>>>(
        skip, wts, b_skip, s_ptr, sum_s, ssq_s);

    gemm1_kernel<<<dim3(2, N_IN / 128), 256, SMEM_H>>>(
        feat_h, wtp, b_proj, h_ptr, sum_p, ssq_p);

    finalize_kernel<<<1, 256>>>(gamma_p, beta_p, gamma_s, beta_s);

    fuse_out_kernel<<<(N_OUT * 64) / 256, 256>>>(cluster, out);
}

// round 16
// speedup vs baseline: 1.0285x; 1.0194x over previous
#include <cuda_runtime.h>
#include <cuda_fp16.h>
#include <cstdint>

// ---------------------------------------------------------------------------
// UnpoolWithSkip — R16: R15 + ONE isolated change: g_s stored fp16
// (GEMM2 epilogue __half2 stores; fuse reads s as half2). g_h stays fp32.
// BN stats remain fp32 (computed from accumulators pre-rounding).
// ---------------------------------------------------------------------------

#define EPS 1e-5f

static constexpr int N_IN  = 65536;
static constexpr int N_OUT = 262144;
static constexpr int C     = 256;

__device__ float  g_h[(size_t)N_IN  * C];
__device__ __half g_s[(size_t)N_OUT * C];
__device__ __half g_feat_h[(size_t)N_IN  * 512];
__device__ __half g_wt_proj[(size_t)C * 512];
__device__ __half g_wt_skip[(size_t)C * 256];
__device__ float g_sum_p[C], g_ssq_p[C];
__device__ float g_sum_s[C], g_ssq_s[C];
__device__ float g_a_p[C], g_b_p[C];
__device__ float g_a_s[C], g_b_s[C];

// ---------------------------------------------------------------------------
__device__ __forceinline__ void mma_f16(float* c, const uint32_t* a, const uint32_t* b) {
    asm volatile(
        "mma.sync.aligned.m16n8k16.row.col.f32.f16.f16.f32 "
        "{%0,%1,%2,%3}, {%4,%5,%6,%7}, {%8,%9}, {%0,%1,%2,%3};"
        : "+f"(c[0]), "+f"(c[1]), "+f"(c[2]), "+f"(c[3])
        : "r"(a[0]), "r"(a[1]), "r"(a[2]), "r"(a[3]), "r"(b[0]), "r"(b[1]));
}
__device__ __forceinline__ void ldsm_x4(uint32_t& d0, uint32_t& d1,
                                        uint32_t& d2, uint32_t& d3, uint32_t addr) {
    asm volatile("ldmatrix.sync.aligned.m8n8.x4.shared.b16 {%0,%1,%2,%3}, [%4];"
                 : "=r"(d0), "=r"(d1), "=r"(d2), "=r"(d3) : "r"(addr));
}
__device__ __forceinline__ uint32_t smem_u32(const void* p) {
    uint32_t a;
    asm("{ .reg .u64 t; cvta.to.shared.u64 t, %1; cvt.u32.u64 %0, t; }"
        : "=r"(a) : "l"(p));
    return a;
}
__device__ __forceinline__ uint32_t pack_h2(float2 v) {
    __half2 h = __floats2half2_rn(v.x, v.y);
    return *(uint32_t*)&h;
}

// ---------------------------------------------------------------------------
__global__ void zero_stats_kernel() {
    int c = threadIdx.x;
    g_sum_p[c] = 0.f; g_ssq_p[c] = 0.f;
    g_sum_s[c] = 0.f; g_ssq_s[c] = 0.f;
}

__global__ __launch_bounds__(256) void f2h_kernel(
    const float* __restrict__ src, __half* __restrict__ dst)
{
    size_t i = ((size_t)blockIdx.x * 256 + threadIdx.x) * 8;
    float4 a = *(const float4*)(src + i);
    float4 b = *(const float4*)(src + i + 4);
    __half2 h[4];
    h[0] = __floats2half2_rn(a.x, a.y);
    h[1] = __floats2half2_rn(a.z, a.w);
    h[2] = __floats2half2_rn(b.x, b.y);
    h[3] = __floats2half2_rn(b.z, b.w);
    *(uint4*)(dst + i) = *(uint4*)h;
}

__global__ void transpose_w_kernel(const float* __restrict__ W,
                                   __half* __restrict__ Wt, int K, int N) {
    __shared__ float t[32][33];
    int n0 = blockIdx.x * 32, k0 = blockIdx.y * 32;
    int tx = threadIdx.x, ty = threadIdx.y;
    #pragma unroll
    for (int i = 0; i < 32; i += 8)
        t[ty + i][tx] = W[(size_t)(k0 + ty + i) * N + n0 + tx];
    __syncthreads();
    #pragma unroll
    for (int i = 0; i < 32; i += 8)
        Wt[(size_t)(n0 + ty + i) * K + k0 + tx] = __float2half_rn(t[tx][ty + i]);
}

__global__ void finalize_kernel(
    const float* __restrict__ gamma_p, const float* __restrict__ beta_p,
    const float* __restrict__ gamma_s, const float* __restrict__ beta_s)
{
    int c = threadIdx.x;
    {
        float m = g_sum_p[c] * (1.f / N_IN);
        float v = g_ssq_p[c] * (1.f / N_IN) - m * m;
        float a = gamma_p[c] * rsqrtf(v + EPS);
        g_a_p[c] = a; g_b_p[c] = beta_p[c] - m * a;
    }
    {
        float m = g_sum_s[c] * (1.f / N_OUT);
        float v = g_ssq_s[c] * (1.f / N_OUT) - m * m;
        float a = gamma_s[c] * rsqrtf(v + EPS);
        g_a_s[c] = a; g_b_s[c] = beta_s[c] - m * a;
    }
}

// out[n,c4..c4+3]: h from fp32, s from fp16.
__global__ __launch_bounds__(256) void fuse_out_kernel(
    const int* __restrict__ cluster, float* __restrict__ out)
{
    int idx = blockIdx.x * 256 + threadIdx.x;
    int n  = idx >> 6;
    int c4 = (idx & 63) << 2;
    int k  = __ldg(&cluster[n]);

    float4 h  = *(const float4*)&g_h[(size_t)k * C + c4];
    uint2 sraw = *(const uint2*)&g_s[(size_t)n * C + c4];
    float2 s01 = __half22float2(*(const __half2*)&sraw.x);
    float2 s23 = __half22float2(*(const __half2*)&sraw.y);
    float4 ap = *(const float4*)&g_a_p[c4];
    float4 bp = *(const float4*)&g_b_p[c4];
    float4 as_ = *(const float4*)&g_a_s[c4];
    float4 bs_ = *(const float4*)&g_b_s[c4];

    float4 o;
    o.x = fmaxf(fmaf(ap.x, h.x, bp.x), 0.f) + fmaxf(fmaf(as_.x, s01.x, bs_.x), 0.f);
    o.y = fmaxf(fmaf(ap.y, h.y, bp.y), 0.f) + fmaxf(fmaf(as_.y, s01.y, bs_.y), 0.f);
    o.z = fmaxf(fmaf(ap.z, h.z, bp.z), 0.f) + fmaxf(fmaf(as_.z, s23.x, bs_.z), 0.f);
    o.w = fmaxf(fmaf(ap.w, h.w, bp.w), 0.f) + fmaxf(fmaf(as_.w, s23.y, bs_.w), 0.f);
    *(float4*)&out[(size_t)n * C + c4] = o;
}

// ---------------------------------------------------------------------------
// GEMM2: g_s(fp16) = skip(fp32 direct) @ wts^T + b_skip. fp32 A in smem,
// consumer float2->half2. Tile 128x128, BK=64, 2-stage, grid (2, 2048).
// ---------------------------------------------------------------------------
static constexpr int A_PADF   = 68;
static constexpr int A_ROWB   = A_PADF * 4;                // 272 B
static constexpr uint32_t A_SB = 128u * A_ROWB;            // 34816 B
static constexpr int B_PADH   = 72;
static constexpr int B_ROWB   = B_PADH * 2;                // 144 B
static constexpr uint32_t BB  = 128u * B_ROWB;             // 18432 B
static constexpr uint32_t ST_F32 = A_SB + BB;              // 53248 B
static constexpr uint32_t SMEM_F32 = ST_F32 * 2;           // 106496 B

__device__ __forceinline__ void load_tile_f32(
    const float* __restrict__ A, const __half* __restrict__ Bt, int K,
    int m0, int n0, int kt, uint32_t sbase, int tid)
{
    #pragma unroll
    for (int p = 0; p < 8; p++) {
        int idx = tid + p * 256;
        int row = idx >> 4, ch = idx & 15;
        const float* ga = A + (size_t)(m0 + row) * K + kt * 64 + ch * 4;
        uint32_t sa = sbase + row * A_ROWB + ch * 16;
        asm volatile("cp.async.cg.shared.global [%0], [%1], 16;"
                     :: "r"(sa), "l"(ga) : "memory");
    }
    #pragma unroll
    for (int p = 0; p < 4; p++) {
        int idx = tid + p * 256;
        int row = idx >> 3, ch = idx & 7;
        const __half* gb = Bt + (size_t)(n0 + row) * K + kt * 64 + ch * 8;
        uint32_t sb = sbase + A_SB + row * B_ROWB + ch * 16;
        asm volatile("cp.async.cg.shared.global [%0], [%1], 16;"
                     :: "r"(sb), "l"(gb) : "memory");
    }
    asm volatile("cp.async.commit_group;" ::: "memory");
}

__global__ __launch_bounds__(256) void gemm2_kernel(
    const float* __restrict__ A, const __half* __restrict__ Bt,
    const float* __restrict__ bias, __half* __restrict__ Cout,
    float* __restrict__ sum, float* __restrict__ ssq)
{
    extern __shared__ char smem_raw[];
    __shared__ float ssum[128], sssq[128];

    const int tid  = threadIdx.x;
    const int lane = tid & 31;
    const int wid  = tid >> 5;
    const int wm   = wid & 3;
    const int wn   = wid >> 2;
    const int g    = lane >> 2;
    const int t    = lane & 3;

    const int n0 = blockIdx.x * 128;
    const int m0 = blockIdx.y * 128;
    const int K  = 256;

    const uint32_t sbase = smem_u32(smem_raw);

    if (tid < 128) { ssum[tid] = 0.f; sssq[tid] = 0.f; }

    float acc[2][8][4];
    #pragma unroll
    for (int i = 0; i < 2; i++)
        #pragma unroll
        for (int j = 0; j < 8; j++)
            #pragma unroll
            for (int q = 0; q < 4; q++) acc[i][j][q] = 0.f;

    const int KT = K >> 6;
    const int mw = wm * 32;
    const int nw = wn * 64;

    const int lm = lane >> 3;
    const int lr = lane & 7;
    uint32_t b_off[4];
    #pragma unroll
    for (int p = 0; p < 4; p++)
        b_off[p] = A_SB
                 + (uint32_t)((nw + 16 * p + 8 * (lm >> 1) + lr) * B_ROWB
                              + (lm & 1) * 16);

    load_tile_f32(A, Bt, K, m0, n0, 0, sbase, tid);

    int buf = 0;
    for (int kt = 0; kt < KT; kt++) {
        if (kt + 1 < KT) {
            load_tile_f32(A, Bt, K, m0, n0, kt + 1,
                          sbase + (uint32_t)(buf ^ 1) * ST_F32, tid);
            asm volatile("cp.async.wait_group 1;" ::: "memory");
        } else {
            asm volatile("cp.async.wait_group 0;" ::: "memory");
        }
        __syncthreads();

        const uint32_t stg = sbase + (uint32_t)buf * ST_F32;
        const float2* Af = (const float2*)(smem_raw + (size_t)buf * ST_F32);

        #pragma unroll
        for (int ks = 0; ks < 4; ks++) {
            const int kf2 = ks * 8 + t;
            uint32_t af[2][4];
            #pragma unroll
            for (int i = 0; i < 2; i++) {
                const int r0 = (mw + i * 16 + g) * (A_PADF / 2);
                const int r1 = r0 + 8 * (A_PADF / 2);
                af[i][0] = pack_h2(Af[r0 + kf2]);
                af[i][1] = pack_h2(Af[r1 + kf2]);
                af[i][2] = pack_h2(Af[r0 + kf2 + 4]);
                af[i][3] = pack_h2(Af[r1 + kf2 + 4]);
            }
            const uint32_t kb = ks * 32;
            uint32_t bf[8][2];
            #pragma unroll
            for (int p = 0; p < 4; p++)
                ldsm_x4(bf[2*p][0], bf[2*p][1], bf[2*p+1][0], bf[2*p+1][1],
                        stg + b_off[p] + kb);
            #pragma unroll
            for (int i = 0; i < 2; i++)
                #pragma unroll
                for (int j = 0; j < 8; j++)
                    mma_f16(acc[i][j], af[i], bf[j]);
        }
        __syncthreads();
        buf ^= 1;
    }

    // ---- Epilogue: bias add, fp16 stores (half2), fp32 BN stats ----
    #pragma unroll
    for (int j = 0; j < 8; j++) {
        const int cl = nw + j * 8 + 2 * t;
        const int cg = n0 + cl;
        const float b0v = __ldg(&bias[cg]);
        const float b1v = __ldg(&bias[cg + 1]);
        float s0 = 0.f, s1 = 0.f, q0 = 0.f, q1 = 0.f;
        #pragma unroll
        for (int i = 0; i < 2; i++) {
            const int row = m0 + mw + i * 16 + g;
            float v00 = acc[i][j][0] + b0v;
            float v01 = acc[i][j][1] + b1v;
            float v10 = acc[i][j][2] + b0v;
            float v11 = acc[i][j][3] + b1v;
            *(__half2*)&Cout[(size_t)row * C + cg]       = __floats2half2_rn(v00, v01);
            *(__half2*)&Cout[(size_t)(row + 8) * C + cg] = __floats2half2_rn(v10, v11);
            s0 += v00 + v10;  s1 += v01 + v11;
            q0 += v00 * v00 + v10 * v10;
            q1 += v01 * v01 + v11 * v11;
        }
        atomicAdd(&ssum[cl], s0);     atomicAdd(&ssum[cl + 1], s1);
        atomicAdd(&sssq[cl], q0);     atomicAdd(&sssq[cl + 1], q1);
    }
    __syncthreads();
    if (tid < 128) {
        atomicAdd(&sum[n0 + tid], ssum[tid]);
        atomicAdd(&ssq[n0 + tid], sssq[tid]);
    }
}

// ---------------------------------------------------------------------------
// GEMM1 (R12 body): g_h(fp32) = feat_h(fp16) @ wtp^T + b_proj. Grid (2, 512).
// ---------------------------------------------------------------------------
static constexpr int H_PADH  = 72;
static constexpr int H_ROWB  = H_PADH * 2;                 // 144
static constexpr uint32_t H_AB = 128u * H_ROWB;            // 18432
static constexpr uint32_t ST_H = H_AB * 2;                 // 36864
static constexpr int H_STAGES = 3;
static constexpr uint32_t SMEM_H = ST_H * H_STAGES;        // 110592

__device__ __forceinline__ void load_tile_h16(
    const __half* __restrict__ A, const __half* __restrict__ Bt, int K,
    int m0, int n0, int kt, uint32_t sbase, int tid)
{
    #pragma unroll
    for (int p = 0; p < 4; p++) {
        int idx = tid + p * 256;
        int row = idx >> 3, ch = idx & 7;
        const __half* ga = A + (size_t)(m0 + row) * K + kt * 64 + ch * 8;
        uint32_t sa = sbase + row * H_ROWB + ch * 16;
        asm volatile("cp.async.cg.shared.global [%0], [%1], 16;"
                     :: "r"(sa), "l"(ga) : "memory");
        const __half* gb = Bt + (size_t)(n0 + row) * K + kt * 64 + ch * 8;
        uint32_t sb = sbase + H_AB + row * H_ROWB + ch * 16;
        asm volatile("cp.async.cg.shared.global [%0], [%1], 16;"
                     :: "r"(sb), "l"(gb) : "memory");
    }
    asm volatile("cp.async.commit_group;" ::: "memory");
}

__global__ __launch_bounds__(256) void gemm1_kernel(
    const __half* __restrict__ A, const __half* __restrict__ Bt,
    const float* __restrict__ bias, float* __restrict__ Cout,
    float* __restrict__ sum, float* __restrict__ ssq)
{
    extern __shared__ char smem_raw[];
    __shared__ float ssum[128], sssq[128];

    const int tid  = threadIdx.x;
    const int lane = tid & 31;
    const int wid  = tid >> 5;
    const int wm   = wid & 3;
    const int wn   = wid >> 2;
    const int g    = lane >> 2;
    const int t    = lane & 3;

    const int n0 = blockIdx.x * 128;
    const int m0 = blockIdx.y * 128;
    const int K  = 512;

    const uint32_t sbase = smem_u32(smem_raw);

    if (tid < 128) { ssum[tid] = 0.f; sssq[tid] = 0.f; }

    float acc[2][8][4];
    #pragma unroll
    for (int i = 0; i < 2; i++)
        #pragma unroll
        for (int j = 0; j < 8; j++)
            #pragma unroll
            for (int q = 0; q < 4; q++) acc[i][j][q] = 0.f;

    const int KT = K >> 6;
    const int mw = wm * 32;
    const int nw = wn * 64;

    const int lm = lane >> 3;
    const int lr = lane & 7;
    uint32_t a_off[2];
    #pragma unroll
    for (int i = 0; i < 2; i++)
        a_off[i] = (uint32_t)((mw + i * 16 + (lm & 1) * 8 + lr) * H_ROWB
                              + (lm >> 1) * 16);
    uint32_t b_off[4];
    #pragma unroll
    for (int p = 0; p < 4; p++)
        b_off[p] = H_AB
                 + (uint32_t)((nw + 16 * p + 8 * (lm >> 1) + lr) * H_ROWB
                              + (lm & 1) * 16);

    load_tile_h16(A, Bt, K, m0, n0, 0, sbase, tid);
    load_tile_h16(A, Bt, K, m0, n0, 1, sbase + ST_H, tid);

    int buf = 0;
    for (int kt = 0; kt < KT; kt++) {
        if (kt >= KT - 2)
            asm volatile("cp.async.wait_group 0;" ::: "memory");
        else
            asm volatile("cp.async.wait_group 1;" ::: "memory");
        __syncthreads();

        if (kt + 2 < KT) {
            int nb = buf + 2; if (nb >= H_STAGES) nb -= H_STAGES;
            load_tile_h16(A, Bt, K, m0, n0, kt + 2,
                          sbase + (uint32_t)nb * ST_H, tid);
        }

        const uint32_t stg = sbase + (uint32_t)buf * ST_H;

        #pragma unroll
        for (int ks = 0; ks < 4; ks++) {
            const uint32_t kb = ks * 32;
            uint32_t af[2][4];
            ldsm_x4(af[0][0], af[0][1], af[0][2], af[0][3], stg + a_off[0] + kb);
            ldsm_x4(af[1][0], af[1][1], af[1][2], af[1][3], stg + a_off[1] + kb);
            uint32_t bf[8][2];
            #pragma unroll
            for (int p = 0; p < 4; p++)
                ldsm_x4(bf[2*p][0], bf[2*p][1], bf[2*p+1][0], bf[2*p+1][1],
                        stg + b_off[p] + kb);
            #pragma unroll
            for (int i = 0; i < 2; i++)
                #pragma unroll
                for (int j = 0; j < 8; j++)
                    mma_f16(acc[i][j], af[i], bf[j]);
        }

        buf++; if (buf == H_STAGES) buf = 0;
    }
    __syncthreads();

    #pragma unroll
    for (int j = 0; j < 8; j++) {
        const int cl = nw + j * 8 + 2 * t;
        const int cg = n0 + cl;
        const float b0v = __ldg(&bias[cg]);
        const float b1v = __ldg(&bias[cg + 1]);
        float s0 = 0.f, s1 = 0.f, q0 = 0.f, q1 = 0.f;
        #pragma unroll
        for (int i = 0; i < 2; i++) {
            const int row = m0 + mw + i * 16 + g;
            float v00 = acc[i][j][0] + b0v;
            float v01 = acc[i][j][1] + b1v;
            float v10 = acc[i][j][2] + b0v;
            float v11 = acc[i][j][3] + b1v;
            float2 lo; lo.x = v00; lo.y = v01;
            float2 hi; hi.x = v10; hi.y = v11;
            *(float2*)&Cout[(size_t)row * C + cg] = lo;
            *(float2*)&Cout[(size_t)(row + 8) * C + cg] = hi;
            s0 += v00 + v10;  s1 += v01 + v11;
            q0 += v00 * v00 + v10 * v10;
            q1 += v01 * v01 + v11 * v11;
        }
        atomicAdd(&ssum[cl], s0);     atomicAdd(&ssum[cl + 1], s1);
        atomicAdd(&sssq[cl], q0);     atomicAdd(&sssq[cl + 1], q1);
    }
    __syncthreads();
    if (tid < 128) {
        atomicAdd(&sum[n0 + tid], ssum[tid]);
        atomicAdd(&ssq[n0 + tid], sssq[tid]);
    }
}

// ---------------------------------------------------------------------------
extern "C" void kernel_launch(void* const* d_in, const int* in_sizes, int n_in,
                              void* d_out, int out_size)
{
    const float* feat    = (const float*)d_in[0];
    const float* skip    = (const float*)d_in[1];
    const int*   cluster = (const int*)  d_in[2];
    const float* W_proj  = (const float*)d_in[3];
    const float* b_proj  = (const float*)d_in[4];
    const float* gamma_p = (const float*)d_in[5];
    const float* beta_p  = (const float*)d_in[6];
    const float* W_skip  = (const float*)d_in[7];
    const float* b_skip  = (const float*)d_in[8];
    const float* gamma_s = (const float*)d_in[9];
    const float* beta_s  = (const float*)d_in[10];
    float* out = (float*)d_out;

    float *h_ptr, *sum_p, *ssq_p, *sum_s, *ssq_s;
    __half *s_ptr, *feat_h, *wtp, *wts;
    cudaGetSymbolAddress((void**)&h_ptr, g_h);
    cudaGetSymbolAddress((void**)&s_ptr, g_s);
    cudaGetSymbolAddress((void**)&feat_h, g_feat_h);
    cudaGetSymbolAddress((void**)&wtp, g_wt_proj);
    cudaGetSymbolAddress((void**)&wts, g_wt_skip);
    cudaGetSymbolAddress((void**)&sum_p, g_sum_p);
    cudaGetSymbolAddress((void**)&ssq_p, g_ssq_p);
    cudaGetSymbolAddress((void**)&sum_s, g_sum_s);
    cudaGetSymbolAddress((void**)&ssq_s, g_ssq_s);

    cudaFuncSetAttribute(gemm2_kernel,
                         cudaFuncAttributeMaxDynamicSharedMemorySize, SMEM_F32);
    cudaFuncSetAttribute(gemm1_kernel,
                         cudaFuncAttributeMaxDynamicSharedMemorySize, SMEM_H);

    zero_stats_kernel<<<1, 256>>>();

    transpose_w_kernel<<<dim3(256 / 32, 512 / 32), dim3(32, 8)>>>(W_proj, wtp, 512, 256);
    transpose_w_kernel<<<dim3(256 / 32, 256 / 32), dim3(32, 8)>>>(W_skip, wts, 256, 256);

    f2h_kernel<<<(int)(((size_t)N_IN * 512) / 2048), 256>>>(feat, feat_h);

    // GEMM2 first (big), GEMM1 last so g_h stays L2-warm for the gather.
    gemm2_kernel<<<dim3(2, N_OUT / 128), 256, SMEM_F32>>>(
        skip, wts, b_skip, s_ptr, sum_s, ssq_s);

    gemm1_kernel<<<dim3(2, N_IN / 128), 256, SMEM_H>>>(
        feat_h, wtp, b_proj, h_ptr, sum_p, ssq_p);

    finalize_kernel<<<1, 256>>>(gamma_p, beta_p, gamma_s, beta_s);

    fuse_out_kernel<<<(N_OUT * 64) / 256, 256>>>(cluster, out);
}

// round 17
// speedup vs baseline: 1.0370x; 1.0083x over previous
#include <cuda_runtime.h>
#include <cuda_fp16.h>
#include <cstdint>

// ---------------------------------------------------------------------------
// UnpoolWithSkip — R17: R16 + ONE isolated change: g_h stored fp16 too
// (GEMM1 epilogue half2 stores; fuse reads h as half2). BN stats stay fp32
// (from accumulators pre-rounding).
// ---------------------------------------------------------------------------

#define EPS 1e-5f

static constexpr int N_IN  = 65536;
static constexpr int N_OUT = 262144;
static constexpr int C     = 256;

__device__ __half g_h[(size_t)N_IN  * C];
__device__ __half g_s[(size_t)N_OUT * C];
__device__ __half g_feat_h[(size_t)N_IN  * 512];
__device__ __half g_wt_proj[(size_t)C * 512];
__device__ __half g_wt_skip[(size_t)C * 256];
__device__ float g_sum_p[C], g_ssq_p[C];
__device__ float g_sum_s[C], g_ssq_s[C];
__device__ float g_a_p[C], g_b_p[C];
__device__ float g_a_s[C], g_b_s[C];

// ---------------------------------------------------------------------------
__device__ __forceinline__ void mma_f16(float* c, const uint32_t* a, const uint32_t* b) {
    asm volatile(
        "mma.sync.aligned.m16n8k16.row.col.f32.f16.f16.f32 "
        "{%0,%1,%2,%3}, {%4,%5,%6,%7}, {%8,%9}, {%0,%1,%2,%3};"
        : "+f"(c[0]), "+f"(c[1]), "+f"(c[2]), "+f"(c[3])
        : "r"(a[0]), "r"(a[1]), "r"(a[2]), "r"(a[3]), "r"(b[0]), "r"(b[1]));
}
__device__ __forceinline__ void ldsm_x4(uint32_t& d0, uint32_t& d1,
                                        uint32_t& d2, uint32_t& d3, uint32_t addr) {
    asm volatile("ldmatrix.sync.aligned.m8n8.x4.shared.b16 {%0,%1,%2,%3}, [%4];"
                 : "=r"(d0), "=r"(d1), "=r"(d2), "=r"(d3) : "r"(addr));
}
__device__ __forceinline__ uint32_t smem_u32(const void* p) {
    uint32_t a;
    asm("{ .reg .u64 t; cvta.to.shared.u64 t, %1; cvt.u32.u64 %0, t; }"
        : "=r"(a) : "l"(p));
    return a;
}
__device__ __forceinline__ uint32_t pack_h2(float2 v) {
    __half2 h = __floats2half2_rn(v.x, v.y);
    return *(uint32_t*)&h;
}

// ---------------------------------------------------------------------------
__global__ void zero_stats_kernel() {
    int c = threadIdx.x;
    g_sum_p[c] = 0.f; g_ssq_p[c] = 0.f;
    g_sum_s[c] = 0.f; g_ssq_s[c] = 0.f;
}

__global__ __launch_bounds__(256) void f2h_kernel(
    const float* __restrict__ src, __half* __restrict__ dst)
{
    size_t i = ((size_t)blockIdx.x * 256 + threadIdx.x) * 8;
    float4 a = *(const float4*)(src + i);
    float4 b = *(const float4*)(src + i + 4);
    __half2 h[4];
    h[0] = __floats2half2_rn(a.x, a.y);
    h[1] = __floats2half2_rn(a.z, a.w);
    h[2] = __floats2half2_rn(b.x, b.y);
    h[3] = __floats2half2_rn(b.z, b.w);
    *(uint4*)(dst + i) = *(uint4*)h;
}

__global__ void transpose_w_kernel(const float* __restrict__ W,
                                   __half* __restrict__ Wt, int K, int N) {
    __shared__ float t[32][33];
    int n0 = blockIdx.x * 32, k0 = blockIdx.y * 32;
    int tx = threadIdx.x, ty = threadIdx.y;
    #pragma unroll
    for (int i = 0; i < 32; i += 8)
        t[ty + i][tx] = W[(size_t)(k0 + ty + i) * N + n0 + tx];
    __syncthreads();
    #pragma unroll
    for (int i = 0; i < 32; i += 8)
        Wt[(size_t)(n0 + ty + i) * K + k0 + tx] = __float2half_rn(t[tx][ty + i]);
}

__global__ void finalize_kernel(
    const float* __restrict__ gamma_p, const float* __restrict__ beta_p,
    const float* __restrict__ gamma_s, const float* __restrict__ beta_s)
{
    int c = threadIdx.x;
    {
        float m = g_sum_p[c] * (1.f / N_IN);
        float v = g_ssq_p[c] * (1.f / N_IN) - m * m;
        float a = gamma_p[c] * rsqrtf(v + EPS);
        g_a_p[c] = a; g_b_p[c] = beta_p[c] - m * a;
    }
    {
        float m = g_sum_s[c] * (1.f / N_OUT);
        float v = g_ssq_s[c] * (1.f / N_OUT) - m * m;
        float a = gamma_s[c] * rsqrtf(v + EPS);
        g_a_s[c] = a; g_b_s[c] = beta_s[c] - m * a;
    }
}

// out[n,c4..c4+3]: h and s both fp16 scratch.
__global__ __launch_bounds__(256) void fuse_out_kernel(
    const int* __restrict__ cluster, float* __restrict__ out)
{
    int idx = blockIdx.x * 256 + threadIdx.x;
    int n  = idx >> 6;
    int c4 = (idx & 63) << 2;
    int k  = __ldg(&cluster[n]);

    uint2 hraw = *(const uint2*)&g_h[(size_t)k * C + c4];
    uint2 sraw = *(const uint2*)&g_s[(size_t)n * C + c4];
    float2 h01 = __half22float2(*(const __half2*)&hraw.x);
    float2 h23 = __half22float2(*(const __half2*)&hraw.y);
    float2 s01 = __half22float2(*(const __half2*)&sraw.x);
    float2 s23 = __half22float2(*(const __half2*)&sraw.y);
    float4 ap = *(const float4*)&g_a_p[c4];
    float4 bp = *(const float4*)&g_b_p[c4];
    float4 as_ = *(const float4*)&g_a_s[c4];
    float4 bs_ = *(const float4*)&g_b_s[c4];

    float4 o;
    o.x = fmaxf(fmaf(ap.x, h01.x, bp.x), 0.f) + fmaxf(fmaf(as_.x, s01.x, bs_.x), 0.f);
    o.y = fmaxf(fmaf(ap.y, h01.y, bp.y), 0.f) + fmaxf(fmaf(as_.y, s01.y, bs_.y), 0.f);
    o.z = fmaxf(fmaf(ap.z, h23.x, bp.z), 0.f) + fmaxf(fmaf(as_.z, s23.x, bs_.z), 0.f);
    o.w = fmaxf(fmaf(ap.w, h23.y, bp.w), 0.f) + fmaxf(fmaf(as_.w, s23.y, bs_.w), 0.f);
    *(float4*)&out[(size_t)n * C + c4] = o;
}

// ---------------------------------------------------------------------------
// GEMM2: g_s(fp16) = skip(fp32 direct) @ wts^T + b_skip. Tile 128x128,
// BK=64, 2-stage, grid (2, 2048).
// ---------------------------------------------------------------------------
static constexpr int A_PADF   = 68;
static constexpr int A_ROWB   = A_PADF * 4;                // 272 B
static constexpr uint32_t A_SB = 128u * A_ROWB;            // 34816 B
static constexpr int B_PADH   = 72;
static constexpr int B_ROWB   = B_PADH * 2;                // 144 B
static constexpr uint32_t BB  = 128u * B_ROWB;             // 18432 B
static constexpr uint32_t ST_F32 = A_SB + BB;              // 53248 B
static constexpr uint32_t SMEM_F32 = ST_F32 * 2;           // 106496 B

__device__ __forceinline__ void load_tile_f32(
    const float* __restrict__ A, const __half* __restrict__ Bt, int K,
    int m0, int n0, int kt, uint32_t sbase, int tid)
{
    #pragma unroll
    for (int p = 0; p < 8; p++) {
        int idx = tid + p * 256;
        int row = idx >> 4, ch = idx & 15;
        const float* ga = A + (size_t)(m0 + row) * K + kt * 64 + ch * 4;
        uint32_t sa = sbase + row * A_ROWB + ch * 16;
        asm volatile("cp.async.cg.shared.global [%0], [%1], 16;"
                     :: "r"(sa), "l"(ga) : "memory");
    }
    #pragma unroll
    for (int p = 0; p < 4; p++) {
        int idx = tid + p * 256;
        int row = idx >> 3, ch = idx & 7;
        const __half* gb = Bt + (size_t)(n0 + row) * K + kt * 64 + ch * 8;
        uint32_t sb = sbase + A_SB + row * B_ROWB + ch * 16;
        asm volatile("cp.async.cg.shared.global [%0], [%1], 16;"
                     :: "r"(sb), "l"(gb) : "memory");
    }
    asm volatile("cp.async.commit_group;" ::: "memory");
}

__global__ __launch_bounds__(256) void gemm2_kernel(
    const float* __restrict__ A, const __half* __restrict__ Bt,
    const float* __restrict__ bias, __half* __restrict__ Cout,
    float* __restrict__ sum, float* __restrict__ ssq)
{
    extern __shared__ char smem_raw[];
    __shared__ float ssum[128], sssq[128];

    const int tid  = threadIdx.x;
    const int lane = tid & 31;
    const int wid  = tid >> 5;
    const int wm   = wid & 3;
    const int wn   = wid >> 2;
    const int g    = lane >> 2;
    const int t    = lane & 3;

    const int n0 = blockIdx.x * 128;
    const int m0 = blockIdx.y * 128;
    const int K  = 256;

    const uint32_t sbase = smem_u32(smem_raw);

    if (tid < 128) { ssum[tid] = 0.f; sssq[tid] = 0.f; }

    float acc[2][8][4];
    #pragma unroll
    for (int i = 0; i < 2; i++)
        #pragma unroll
        for (int j = 0; j < 8; j++)
            #pragma unroll
            for (int q = 0; q < 4; q++) acc[i][j][q] = 0.f;

    const int KT = K >> 6;
    const int mw = wm * 32;
    const int nw = wn * 64;

    const int lm = lane >> 3;
    const int lr = lane & 7;
    uint32_t b_off[4];
    #pragma unroll
    for (int p = 0; p < 4; p++)
        b_off[p] = A_SB
                 + (uint32_t)((nw + 16 * p + 8 * (lm >> 1) + lr) * B_ROWB
                              + (lm & 1) * 16);

    load_tile_f32(A, Bt, K, m0, n0, 0, sbase, tid);

    int buf = 0;
    for (int kt = 0; kt < KT; kt++) {
        if (kt + 1 < KT) {
            load_tile_f32(A, Bt, K, m0, n0, kt + 1,
                          sbase + (uint32_t)(buf ^ 1) * ST_F32, tid);
            asm volatile("cp.async.wait_group 1;" ::: "memory");
        } else {
            asm volatile("cp.async.wait_group 0;" ::: "memory");
        }
        __syncthreads();

        const uint32_t stg = sbase + (uint32_t)buf * ST_F32;
        const float2* Af = (const float2*)(smem_raw + (size_t)buf * ST_F32);

        #pragma unroll
        for (int ks = 0; ks < 4; ks++) {
            const int kf2 = ks * 8 + t;
            uint32_t af[2][4];
            #pragma unroll
            for (int i = 0; i < 2; i++) {
                const int r0 = (mw + i * 16 + g) * (A_PADF / 2);
                const int r1 = r0 + 8 * (A_PADF / 2);
                af[i][0] = pack_h2(Af[r0 + kf2]);
                af[i][1] = pack_h2(Af[r1 + kf2]);
                af[i][2] = pack_h2(Af[r0 + kf2 + 4]);
                af[i][3] = pack_h2(Af[r1 + kf2 + 4]);
            }
            const uint32_t kb = ks * 32;
            uint32_t bf[8][2];
            #pragma unroll
            for (int p = 0; p < 4; p++)
                ldsm_x4(bf[2*p][0], bf[2*p][1], bf[2*p+1][0], bf[2*p+1][1],
                        stg + b_off[p] + kb);
            #pragma unroll
            for (int i = 0; i < 2; i++)
                #pragma unroll
                for (int j = 0; j < 8; j++)
                    mma_f16(acc[i][j], af[i], bf[j]);
        }
        __syncthreads();
        buf ^= 1;
    }

    #pragma unroll
    for (int j = 0; j < 8; j++) {
        const int cl = nw + j * 8 + 2 * t;
        const int cg = n0 + cl;
        const float b0v = __ldg(&bias[cg]);
        const float b1v = __ldg(&bias[cg + 1]);
        float s0 = 0.f, s1 = 0.f, q0 = 0.f, q1 = 0.f;
        #pragma unroll
        for (int i = 0; i < 2; i++) {
            const int row = m0 + mw + i * 16 + g;
            float v00 = acc[i][j][0] + b0v;
            float v01 = acc[i][j][1] + b1v;
            float v10 = acc[i][j][2] + b0v;
            float v11 = acc[i][j][3] + b1v;
            *(__half2*)&Cout[(size_t)row * C + cg]       = __floats2half2_rn(v00, v01);
            *(__half2*)&Cout[(size_t)(row + 8) * C + cg] = __floats2half2_rn(v10, v11);
            s0 += v00 + v10;  s1 += v01 + v11;
            q0 += v00 * v00 + v10 * v10;
            q1 += v01 * v01 + v11 * v11;
        }
        atomicAdd(&ssum[cl], s0);     atomicAdd(&ssum[cl + 1], s1);
        atomicAdd(&sssq[cl], q0);     atomicAdd(&sssq[cl + 1], q1);
    }
    __syncthreads();
    if (tid < 128) {
        atomicAdd(&sum[n0 + tid], ssum[tid]);
        atomicAdd(&ssq[n0 + tid], sssq[tid]);
    }
}

// ---------------------------------------------------------------------------
// GEMM1: g_h(fp16) = feat_h(fp16) @ wtp^T + b_proj. Grid (2, 512).
// ---------------------------------------------------------------------------
static constexpr int H_PADH  = 72;
static constexpr int H_ROWB  = H_PADH * 2;                 // 144
static constexpr uint32_t H_AB = 128u * H_ROWB;            // 18432
static constexpr uint32_t ST_H = H_AB * 2;                 // 36864
static constexpr int H_STAGES = 3;
static constexpr uint32_t SMEM_H = ST_H * H_STAGES;        // 110592

__device__ __forceinline__ void load_tile_h16(
    const __half* __restrict__ A, const __half* __restrict__ Bt, int K,
    int m0, int n0, int kt, uint32_t sbase, int tid)
{
    #pragma unroll
    for (int p = 0; p < 4; p++) {
        int idx = tid + p * 256;
        int row = idx >> 3, ch = idx & 7;
        const __half* ga = A + (size_t)(m0 + row) * K + kt * 64 + ch * 8;
        uint32_t sa = sbase + row * H_ROWB + ch * 16;
        asm volatile("cp.async.cg.shared.global [%0], [%1], 16;"
                     :: "r"(sa), "l"(ga) : "memory");
        const __half* gb = Bt + (size_t)(n0 + row) * K + kt * 64 + ch * 8;
        uint32_t sb = sbase + H_AB + row * H_ROWB + ch * 16;
        asm volatile("cp.async.cg.shared.global [%0], [%1], 16;"
                     :: "r"(sb), "l"(gb) : "memory");
    }
    asm volatile("cp.async.commit_group;" ::: "memory");
}

__global__ __launch_bounds__(256) void gemm1_kernel(
    const __half* __restrict__ A, const __half* __restrict__ Bt,
    const float* __restrict__ bias, __half* __restrict__ Cout,
    float* __restrict__ sum, float* __restrict__ ssq)
{
    extern __shared__ char smem_raw[];
    __shared__ float ssum[128], sssq[128];

    const int tid  = threadIdx.x;
    const int lane = tid & 31;
    const int wid  = tid >> 5;
    const int wm   = wid & 3;
    const int wn   = wid >> 2;
    const int g    = lane >> 2;
    const int t    = lane & 3;

    const int n0 = blockIdx.x * 128;
    const int m0 = blockIdx.y * 128;
    const int K  = 512;

    const uint32_t sbase = smem_u32(smem_raw);

    if (tid < 128) { ssum[tid] = 0.f; sssq[tid] = 0.f; }

    float acc[2][8][4];
    #pragma unroll
    for (int i = 0; i < 2; i++)
        #pragma unroll
        for (int j = 0; j < 8; j++)
            #pragma unroll
            for (int q = 0; q < 4; q++) acc[i][j][q] = 0.f;

    const int KT = K >> 6;
    const int mw = wm * 32;
    const int nw = wn * 64;

    const int lm = lane >> 3;
    const int lr = lane & 7;
    uint32_t a_off[2];
    #pragma unroll
    for (int i = 0; i < 2; i++)
        a_off[i] = (uint32_t)((mw + i * 16 + (lm & 1) * 8 + lr) * H_ROWB
                              + (lm >> 1) * 16);
    uint32_t b_off[4];
    #pragma unroll
    for (int p = 0; p < 4; p++)
        b_off[p] = H_AB
                 + (uint32_t)((nw + 16 * p + 8 * (lm >> 1) + lr) * H_ROWB
                              + (lm & 1) * 16);

    load_tile_h16(A, Bt, K, m0, n0, 0, sbase, tid);
    load_tile_h16(A, Bt, K, m0, n0, 1, sbase + ST_H, tid);

    int buf = 0;
    for (int kt = 0; kt < KT; kt++) {
        if (kt >= KT - 2)
            asm volatile("cp.async.wait_group 0;" ::: "memory");
        else
            asm volatile("cp.async.wait_group 1;" ::: "memory");
        __syncthreads();

        if (kt + 2 < KT) {
            int nb = buf + 2; if (nb >= H_STAGES) nb -= H_STAGES;
            load_tile_h16(A, Bt, K, m0, n0, kt + 2,
                          sbase + (uint32_t)nb * ST_H, tid);
        }

        const uint32_t stg = sbase + (uint32_t)buf * ST_H;

        #pragma unroll
        for (int ks = 0; ks < 4; ks++) {
            const uint32_t kb = ks * 32;
            uint32_t af[2][4];
            ldsm_x4(af[0][0], af[0][1], af[0][2], af[0][3], stg + a_off[0] + kb);
            ldsm_x4(af[1][0], af[1][1], af[1][2], af[1][3], stg + a_off[1] + kb);
            uint32_t bf[8][2];
            #pragma unroll
            for (int p = 0; p < 4; p++)
                ldsm_x4(bf[2*p][0], bf[2*p][1], bf[2*p+1][0], bf[2*p+1][1],
                        stg + b_off[p] + kb);
            #pragma unroll
            for (int i = 0; i < 2; i++)
                #pragma unroll
                for (int j = 0; j < 8; j++)
                    mma_f16(acc[i][j], af[i], bf[j]);
        }

        buf++; if (buf == H_STAGES) buf = 0;
    }
    __syncthreads();

    #pragma unroll
    for (int j = 0; j < 8; j++) {
        const int cl = nw + j * 8 + 2 * t;
        const int cg = n0 + cl;
        const float b0v = __ldg(&bias[cg]);
        const float b1v = __ldg(&bias[cg + 1]);
        float s0 = 0.f, s1 = 0.f, q0 = 0.f, q1 = 0.f;
        #pragma unroll
        for (int i = 0; i < 2; i++) {
            const int row = m0 + mw + i * 16 + g;
            float v00 = acc[i][j][0] + b0v;
            float v01 = acc[i][j][1] + b1v;
            float v10 = acc[i][j][2] + b0v;
            float v11 = acc[i][j][3] + b1v;
            *(__half2*)&Cout[(size_t)row * C + cg]       = __floats2half2_rn(v00, v01);
            *(__half2*)&Cout[(size_t)(row + 8) * C + cg] = __floats2half2_rn(v10, v11);
            s0 += v00 + v10;  s1 += v01 + v11;
            q0 += v00 * v00 + v10 * v10;
            q1 += v01 * v01 + v11 * v11;
        }
        atomicAdd(&ssum[cl], s0);     atomicAdd(&ssum[cl + 1], s1);
        atomicAdd(&sssq[cl], q0);     atomicAdd(&sssq[cl + 1], q1);
    }
    __syncthreads();
    if (tid < 128) {
        atomicAdd(&sum[n0 + tid], ssum[tid]);
        atomicAdd(&ssq[n0 + tid], sssq[tid]);
    }
}

// ---------------------------------------------------------------------------
extern "C" void kernel_launch(void* const* d_in, const int* in_sizes, int n_in,
                              void* d_out, int out_size)
{
    const float* feat    = (const float*)d_in[0];
    const float* skip    = (const float*)d_in[1];
    const int*   cluster = (const int*)  d_in[2];
    const float* W_proj  = (const float*)d_in[3];
    const float* b_proj  = (const float*)d_in[4];
    const float* gamma_p = (const float*)d_in[5];
    const float* beta_p  = (const float*)d_in[6];
    const float* W_skip  = (const float*)d_in[7];
    const float* b_skip  = (const float*)d_in[8];
    const float* gamma_s = (const float*)d_in[9];
    const float* beta_s  = (const float*)d_in[10];
    float* out = (float*)d_out;

    float *sum_p, *ssq_p, *sum_s, *ssq_s;
    __half *h_ptr, *s_ptr, *feat_h, *wtp, *wts;
    cudaGetSymbolAddress((void**)&h_ptr, g_h);
    cudaGetSymbolAddress((void**)&s_ptr, g_s);
    cudaGetSymbolAddress((void**)&feat_h, g_feat_h);
    cudaGetSymbolAddress((void**)&wtp, g_wt_proj);
    cudaGetSymbolAddress((void**)&wts, g_wt_skip);
    cudaGetSymbolAddress((void**)&sum_p, g_sum_p);
    cudaGetSymbolAddress((void**)&ssq_p, g_ssq_p);
    cudaGetSymbolAddress((void**)&sum_s, g_sum_s);
    cudaGetSymbolAddress((void**)&ssq_s, g_ssq_s);

    cudaFuncSetAttribute(gemm2_kernel,
                         cudaFuncAttributeMaxDynamicSharedMemorySize, SMEM_F32);
    cudaFuncSetAttribute(gemm1_kernel,
                         cudaFuncAttributeMaxDynamicSharedMemorySize, SMEM_H);

    zero_stats_kernel<<<1, 256>>>();

    transpose_w_kernel<<<dim3(256 / 32, 512 / 32), dim3(32, 8)>>>(W_proj, wtp, 512, 256);
    transpose_w_kernel<<<dim3(256 / 32, 256 / 32), dim3(32, 8)>>>(W_skip, wts, 256, 256);

    f2h_kernel<<<(int)(((size_t)N_IN * 512) / 2048), 256>>>(feat, feat_h);

    // GEMM2 first (big), GEMM1 last so g_h stays L2-warm for the gather.
    gemm2_kernel<<<dim3(2, N_OUT / 128), 256, SMEM_F32>>>(
        skip, wts, b_skip, s_ptr, sum_s, ssq_s);

    gemm1_kernel<<<dim3(2, N_IN / 128), 256, SMEM_H>>>(
        feat_h, wtp, b_proj, h_ptr, sum_p, ssq_p);

    finalize_kernel<<<1, 256>>>(gamma_p, beta_p, gamma_s, beta_s);

    fuse_out_kernel<<<(N_OUT * 64) / 256, 256>>>(cluster, out);
}